// round 1
// baseline (speedup 1.0000x reference)
#include <cuda_runtime.h>
#include <math.h>
#include <stdint.h>

// Problem constants
constexpr int SEQ    = 4096;
constexpr int DMODEL = 768;
constexpr int NH     = 12;
constexpr int DH     = 64;
constexpr int HALF   = DH / 2;   // 32

// Scratch (device globals; no runtime allocation allowed)
__device__ float g_q[NH * SEQ * DH];
__device__ float g_k[NH * SEQ * DH];
__device__ float g_v[NH * SEQ * DH];
__device__ float g_o[SEQ * DMODEL];
__device__ float g_cos[SEQ * HALF];
__device__ float g_sin[SEQ * HALF];

// ---------------------------------------------------------------------------
// RoPE cos/sin cache — replicate the reference fp32 computation exactly.
// ---------------------------------------------------------------------------
__global__ void rope_cache_kernel(float* __restrict__ c, float* __restrict__ s)
{
    int i = blockIdx.x * blockDim.x + threadIdx.x;
    if (i >= SEQ * HALF) return;
    int p = i >> 5;          // position
    int k = i & 31;          // frequency index
    float expo = -2.0f * (float)k / (float)DH;
    float invf = powf(10000.0f, expo);
    float ang  = (float)p * invf;
    c[i] = cosf(ang);
    s[i] = sinf(ang);
}

// ---------------------------------------------------------------------------
// NT GEMM: C[m][n] = sum_k A[m][k] * B[n][k],  M=4096 (grid.y*128), N=K=768.
// MODE 0: plain store C row-major [M][768]
// MODE 1: RoPE + scale, scatter to [h][s][64]   (Q with scale=0.125, K with 1)
// MODE 2: scatter to [h][s][64], no rope        (V)
// Tile: BM=128, BN=128, BK=16, 256 threads, 8x8 per thread.
// ---------------------------------------------------------------------------
template<int MODE>
__global__ __launch_bounds__(256)
void gemm_nt(const float* __restrict__ A, const float* __restrict__ B,
             float* __restrict__ C, const int* __restrict__ pos,
             const float* __restrict__ cosc, const float* __restrict__ sinc,
             float scale)
{
    constexpr int KD = 768;
    constexpr int N  = 768;
    __shared__ __align__(16) float As[16][132];   // [k][m]
    __shared__ __align__(16) float Bs[16][132];   // [k][n]

    const int tid = threadIdx.x;
    const int m0  = blockIdx.y * 128;
    const int n0  = blockIdx.x * 128;
    const int tm  = tid >> 4;      // 0..15
    const int tn  = tid & 15;      // 0..15

    const int lr = tid >> 2;           // 0..63
    const int lc = (tid & 3) * 4;      // 0,4,8,12

    float acc[8][8];
    #pragma unroll
    for (int i = 0; i < 8; i++)
        #pragma unroll
        for (int j = 0; j < 8; j++) acc[i][j] = 0.0f;

    for (int k0 = 0; k0 < KD; k0 += 16) {
        #pragma unroll
        for (int rr = 0; rr < 2; rr++) {
            int row = lr + rr * 64;
            float4 v = *(const float4*)(A + (size_t)(m0 + row) * KD + k0 + lc);
            As[lc + 0][row] = v.x; As[lc + 1][row] = v.y;
            As[lc + 2][row] = v.z; As[lc + 3][row] = v.w;
        }
        #pragma unroll
        for (int rr = 0; rr < 2; rr++) {
            int row = lr + rr * 64;
            float4 v = *(const float4*)(B + (size_t)(n0 + row) * KD + k0 + lc);
            Bs[lc + 0][row] = v.x; Bs[lc + 1][row] = v.y;
            Bs[lc + 2][row] = v.z; Bs[lc + 3][row] = v.w;
        }
        __syncthreads();
        #pragma unroll
        for (int kk = 0; kk < 16; kk++) {
            float a[8], b[8];
            *(float4*)(a)     = *(const float4*)&As[kk][tm * 8];
            *(float4*)(a + 4) = *(const float4*)&As[kk][tm * 8 + 4];
            *(float4*)(b)     = *(const float4*)&Bs[kk][tn * 8];
            *(float4*)(b + 4) = *(const float4*)&Bs[kk][tn * 8 + 4];
            #pragma unroll
            for (int i = 0; i < 8; i++)
                #pragma unroll
                for (int j = 0; j < 8; j++)
                    acc[i][j] += a[i] * b[j];
        }
        __syncthreads();
    }

    if (MODE == 0) {
        #pragma unroll
        for (int i = 0; i < 8; i++) {
            int mrow = m0 + tm * 8 + i;
            float* dst = C + (size_t)mrow * N + n0 + tn * 8;
            *(float4*)(dst)     = make_float4(acc[i][0], acc[i][1], acc[i][2], acc[i][3]);
            *(float4*)(dst + 4) = make_float4(acc[i][4], acc[i][5], acc[i][6], acc[i][7]);
        }
    } else if (MODE == 1) {
        #pragma unroll
        for (int i = 0; i < 8; i++) {
            int mrow = m0 + tm * 8 + i;
            int p = pos[mrow];
            const float* cr = cosc + (size_t)p * HALF;
            const float* sr = sinc + (size_t)p * HALF;
            #pragma unroll
            for (int jp = 0; jp < 4; jp++) {
                int n  = n0 + tn * 8 + 2 * jp;
                int dh = n & 63;
                int hh = n >> 6;
                float cc = cr[dh >> 1];
                float ss = sr[dh >> 1];
                float e = acc[i][2 * jp];
                float o = acc[i][2 * jp + 1];
                float re = (e * cc - o * ss) * scale;
                float ro = (e * ss + o * cc) * scale;
                float* dst = C + ((size_t)hh * SEQ + mrow) * DH + dh;
                dst[0] = re;
                dst[1] = ro;
            }
        }
    } else { // MODE 2: V scatter
        #pragma unroll
        for (int i = 0; i < 8; i++) {
            int mrow = m0 + tm * 8 + i;
            #pragma unroll
            for (int j = 0; j < 8; j++) {
                int n  = n0 + tn * 8 + j;
                int dh = n & 63;
                int hh = n >> 6;
                C[((size_t)hh * SEQ + mrow) * DH + dh] = acc[i][j];
            }
        }
    }
}

// ---------------------------------------------------------------------------
// Flash attention, causal. One (64-row q-block, head) per CTA.
// 256 threads as 16x16; each thread owns rows {ty+16i} x cols {tx+16u}.
// Scores already scaled (scale folded into Q).
// ---------------------------------------------------------------------------
__global__ __launch_bounds__(256, 2)
void attn_kernel(const float* __restrict__ Q, const float* __restrict__ K,
                 const float* __restrict__ V, float* __restrict__ O)
{
    extern __shared__ float sm[];
    float* Qs = sm;                  // [64][68]  [row][d]
    float* Ks = sm + 64 * 68;        // [64][68]  [col][d]
    float* Vt = sm + 2 * 64 * 68;    // [64][68]  [d][k]   (V transposed)
    float* Ps = sm + 3 * 64 * 68;    // [64][68]  [row][k]

    const int qb = blockIdx.x;
    const int h  = blockIdx.y;
    const int q0 = qb * 64;
    const int tid = threadIdx.x;
    const int tx = tid & 15;
    const int ty = tid >> 4;

    const float* Qh = Q + (size_t)h * SEQ * DH;
    const float* Kh = K + (size_t)h * SEQ * DH;
    const float* Vh = V + (size_t)h * SEQ * DH;

    // Load Q tile (rows q0..q0+63), natural [row][d] layout, padded stride 68.
    {
        int r  = tid >> 2;
        int c0 = (tid & 3) * 16;
        #pragma unroll
        for (int q = 0; q < 4; q++) {
            float4 v = *(const float4*)(Qh + (size_t)(q0 + r) * DH + c0 + 4 * q);
            *(float4*)&Qs[r * 68 + c0 + 4 * q] = v;
        }
    }

    float m[4], l[4], acc[4][4];
    #pragma unroll
    for (int i = 0; i < 4; i++) {
        m[i] = -1e30f;
        l[i] = 0.0f;
        #pragma unroll
        for (int u = 0; u < 4; u++) acc[i][u] = 0.0f;
    }

    for (int kvb = 0; kvb <= qb; kvb++) {
        int k0 = kvb * 64;
        __syncthreads();   // previous PV readers done before overwriting Ks/Vt/Ps

        // Load K tile [col][d] and V tile transposed Vt[d][k]
        {
            int r  = tid >> 2;
            int c0 = (tid & 3) * 16;
            #pragma unroll
            for (int q = 0; q < 4; q++) {
                float4 v = *(const float4*)(Kh + (size_t)(k0 + r) * DH + c0 + 4 * q);
                *(float4*)&Ks[r * 68 + c0 + 4 * q] = v;
            }
            #pragma unroll
            for (int q = 0; q < 4; q++) {
                float4 v = *(const float4*)(Vh + (size_t)(k0 + r) * DH + c0 + 4 * q);
                int d = c0 + 4 * q;
                Vt[(d + 0) * 68 + r] = v.x;
                Vt[(d + 1) * 68 + r] = v.y;
                Vt[(d + 2) * 68 + r] = v.z;
                Vt[(d + 3) * 68 + r] = v.w;
            }
        }
        __syncthreads();

        // S = Q K^T
        float s[4][4];
        #pragma unroll
        for (int i = 0; i < 4; i++)
            #pragma unroll
            for (int j = 0; j < 4; j++) s[i][j] = 0.0f;

        #pragma unroll
        for (int d = 0; d < 64; d += 4) {
            float4 qv[4], kf[4];
            #pragma unroll
            for (int i = 0; i < 4; i++) qv[i] = *(const float4*)&Qs[(ty + 16 * i) * 68 + d];
            #pragma unroll
            for (int j = 0; j < 4; j++) kf[j] = *(const float4*)&Ks[(tx + 16 * j) * 68 + d];
            #pragma unroll
            for (int i = 0; i < 4; i++)
                #pragma unroll
                for (int j = 0; j < 4; j++) {
                    s[i][j] += qv[i].x * kf[j].x;
                    s[i][j] += qv[i].y * kf[j].y;
                    s[i][j] += qv[i].z * kf[j].z;
                    s[i][j] += qv[i].w * kf[j].w;
                }
        }

        if (kvb == qb) {
            #pragma unroll
            for (int i = 0; i < 4; i++) {
                int row = ty + 16 * i;
                #pragma unroll
                for (int j = 0; j < 4; j++) {
                    int col = tx + 16 * j;
                    if (col > row) s[i][j] = -1e30f;
                }
            }
        }

        // Online softmax (row reductions across the 16 tx lanes of this half-warp)
        #pragma unroll
        for (int i = 0; i < 4; i++) {
            float tmax = fmaxf(fmaxf(s[i][0], s[i][1]), fmaxf(s[i][2], s[i][3]));
            #pragma unroll
            for (int w = 8; w >= 1; w >>= 1)
                tmax = fmaxf(tmax, __shfl_xor_sync(0xffffffffu, tmax, w));
            float mn   = fmaxf(m[i], tmax);
            float corr = expf(m[i] - mn);
            float psum = 0.0f;
            #pragma unroll
            for (int j = 0; j < 4; j++) {
                float p = expf(s[i][j] - mn);
                s[i][j] = p;
                psum += p;
            }
            #pragma unroll
            for (int w = 8; w >= 1; w >>= 1)
                psum += __shfl_xor_sync(0xffffffffu, psum, w);
            l[i] = l[i] * corr + psum;
            m[i] = mn;
            #pragma unroll
            for (int u = 0; u < 4; u++) acc[i][u] *= corr;
            #pragma unroll
            for (int j = 0; j < 4; j++)
                Ps[(ty + 16 * i) * 68 + tx + 16 * j] = s[i][j];
        }
        __syncthreads();

        // O += P @ V   (reduce over k; Vt is [d][k])
        #pragma unroll
        for (int k = 0; k < 64; k += 4) {
            float4 pf[4], vf[4];
            #pragma unroll
            for (int i = 0; i < 4; i++) pf[i] = *(const float4*)&Ps[(ty + 16 * i) * 68 + k];
            #pragma unroll
            for (int u = 0; u < 4; u++) vf[u] = *(const float4*)&Vt[(tx + 16 * u) * 68 + k];
            #pragma unroll
            for (int i = 0; i < 4; i++)
                #pragma unroll
                for (int u = 0; u < 4; u++) {
                    acc[i][u] += pf[i].x * vf[u].x;
                    acc[i][u] += pf[i].y * vf[u].y;
                    acc[i][u] += pf[i].z * vf[u].z;
                    acc[i][u] += pf[i].w * vf[u].w;
                }
        }
    }

    // Write O to [s][h*64 + dh]
    #pragma unroll
    for (int i = 0; i < 4; i++) {
        float inv = 1.0f / l[i];
        int srow = q0 + ty + 16 * i;
        #pragma unroll
        for (int u = 0; u < 4; u++)
            O[(size_t)srow * DMODEL + h * DH + tx + 16 * u] = acc[i][u] * inv;
    }
}

// ---------------------------------------------------------------------------
// kernel_launch — graph-capturable, allocation-free.
// Inputs: x[1,4096,768], wq, wk, wv, wo [768,768], token_positions[1,4096] i32
// ---------------------------------------------------------------------------
extern "C" void kernel_launch(void* const* d_in, const int* in_sizes, int n_in,
                              void* d_out, int out_size)
{
    const float* x   = (const float*)d_in[0];
    const float* wq  = (const float*)d_in[1];
    const float* wk  = (const float*)d_in[2];
    const float* wv  = (const float*)d_in[3];
    const float* wo  = (const float*)d_in[4];
    const int*   pos = (const int*)d_in[5];
    float* out = (float*)d_out;

    float *qp, *kp, *vp, *op, *cp, *sp;
    cudaGetSymbolAddress((void**)&qp, g_q);
    cudaGetSymbolAddress((void**)&kp, g_k);
    cudaGetSymbolAddress((void**)&vp, g_v);
    cudaGetSymbolAddress((void**)&op, g_o);
    cudaGetSymbolAddress((void**)&cp, g_cos);
    cudaGetSymbolAddress((void**)&sp, g_sin);

    // 1. RoPE cache (4096 x 32)
    rope_cache_kernel<<<(SEQ * HALF + 255) / 256, 256>>>(cp, sp);

    // 2. Q/K/V projections (RoPE fused into Q/K epilogue, scale into Q)
    dim3 gg(DMODEL / 128, SEQ / 128);
    gemm_nt<1><<<gg, 256>>>(x, wq, qp, pos, cp, sp, 0.125f);
    gemm_nt<1><<<gg, 256>>>(x, wk, kp, pos, cp, sp, 1.0f);
    gemm_nt<2><<<gg, 256>>>(x, wv, vp, nullptr, nullptr, nullptr, 1.0f);

    // 3. Causal flash attention
    const int smem_bytes = 4 * 64 * 68 * (int)sizeof(float);  // 69632
    cudaFuncSetAttribute(attn_kernel, cudaFuncAttributeMaxDynamicSharedMemorySize,
                         smem_bytes);
    attn_kernel<<<dim3(SEQ / 64, NH), 256, smem_bytes>>>(qp, kp, vp, op);

    // 4. Output projection
    gemm_nt<0><<<gg, 256>>>(op, wo, out, nullptr, nullptr, nullptr, 1.0f);
}

// round 2
// speedup vs baseline: 1.2454x; 1.2454x over previous
#include <cuda_runtime.h>
#include <cuda_bf16.h>
#include <math.h>
#include <stdint.h>

using bf16 = __nv_bfloat16;

constexpr int SEQ    = 4096;
constexpr int DMODEL = 768;
constexpr int NH     = 12;
constexpr int DH     = 64;
constexpr int HALF   = DH / 2;   // 32

// Scratch (device globals; no runtime allocation allowed)
__device__ bf16  g_qh[NH * SEQ * DH];
__device__ bf16  g_ql[NH * SEQ * DH];
__device__ bf16  g_kh[NH * SEQ * DH];
__device__ bf16  g_kl[NH * SEQ * DH];
__device__ bf16  g_vh[NH * SEQ * DH];
__device__ bf16  g_vl[NH * SEQ * DH];
__device__ float g_o[SEQ * DMODEL];
__device__ float g_cos[SEQ * HALF];
__device__ float g_sin[SEQ * HALF];

// ---------------------------------------------------------------------------
// RoPE cos/sin cache — replicate the reference fp32 computation.
// ---------------------------------------------------------------------------
__global__ void rope_cache_kernel(float* __restrict__ c, float* __restrict__ s)
{
    int i = blockIdx.x * blockDim.x + threadIdx.x;
    if (i >= SEQ * HALF) return;
    int p = i >> 5;
    int k = i & 31;
    float expo = -2.0f * (float)k / (float)DH;
    float invf = powf(10000.0f, expo);
    float ang  = (float)p * invf;
    c[i] = cosf(ang);
    s[i] = sinf(ang);
}

// ---------------------------------------------------------------------------
// bf16 split helpers
// ---------------------------------------------------------------------------
__device__ __forceinline__ void split_store_pair(bf16* __restrict__ hi_arr,
                                                 bf16* __restrict__ lo_arr,
                                                 size_t idx, float a, float b)
{
    __nv_bfloat162 h = __floats2bfloat162_rn(a, b);
    float ha = __bfloat162float(h.x);
    float hb = __bfloat162float(h.y);
    __nv_bfloat162 l = __floats2bfloat162_rn(a - ha, b - hb);
    *reinterpret_cast<__nv_bfloat162*>(hi_arr + idx) = h;
    *reinterpret_cast<__nv_bfloat162*>(lo_arr + idx) = l;
}

__device__ __forceinline__ void splitpack(float a, float b,
                                          uint32_t& hi, uint32_t& lo)
{
    __nv_bfloat162 h = __floats2bfloat162_rn(a, b);
    float ha = __bfloat162float(h.x);
    float hb = __bfloat162float(h.y);
    __nv_bfloat162 l = __floats2bfloat162_rn(a - ha, b - hb);
    hi = *reinterpret_cast<uint32_t*>(&h);
    lo = *reinterpret_cast<uint32_t*>(&l);
}

// ---------------------------------------------------------------------------
// mma / ldmatrix wrappers
// ---------------------------------------------------------------------------
__device__ __forceinline__ void ldsm4(uint32_t* r, uint32_t addr)
{
    asm volatile("ldmatrix.sync.aligned.m8n8.x4.shared.b16 {%0,%1,%2,%3}, [%4];"
        : "=r"(r[0]), "=r"(r[1]), "=r"(r[2]), "=r"(r[3]) : "r"(addr));
}
__device__ __forceinline__ void ldsm4t(uint32_t* r, uint32_t addr)
{
    asm volatile("ldmatrix.sync.aligned.m8n8.x4.trans.shared.b16 {%0,%1,%2,%3}, [%4];"
        : "=r"(r[0]), "=r"(r[1]), "=r"(r[2]), "=r"(r[3]) : "r"(addr));
}
__device__ __forceinline__ void mma16816(float* d, const uint32_t* a, const uint32_t* b)
{
    asm volatile(
        "mma.sync.aligned.m16n8k16.row.col.f32.bf16.bf16.f32 "
        "{%0,%1,%2,%3}, {%4,%5,%6,%7}, {%8,%9}, {%0,%1,%2,%3};"
        : "+f"(d[0]), "+f"(d[1]), "+f"(d[2]), "+f"(d[3])
        : "r"(a[0]), "r"(a[1]), "r"(a[2]), "r"(a[3]), "r"(b[0]), "r"(b[1]));
}

// ---------------------------------------------------------------------------
// Fused QKV projection: C = x @ W^T for W in {wq, wk, wv} selected by blockIdx.z.
// Epilogue: RoPE (q/k) + scale, then bf16 hi/lo split-store to [h][s][64].
// Tile: 128x128x16, 256 threads, 8x8 per thread.
// ---------------------------------------------------------------------------
__global__ __launch_bounds__(256)
void gemm_qkv(const float* __restrict__ A,
              const float* __restrict__ Wq, const float* __restrict__ Wk,
              const float* __restrict__ Wv,
              bf16* __restrict__ qh, bf16* __restrict__ ql,
              bf16* __restrict__ kh, bf16* __restrict__ kl,
              bf16* __restrict__ vh, bf16* __restrict__ vl,
              const int* __restrict__ pos,
              const float* __restrict__ cosc, const float* __restrict__ sinc)
{
    constexpr int KD = 768;
    __shared__ __align__(16) float As[16][132];
    __shared__ __align__(16) float Bs[16][132];

    const int z   = blockIdx.z;
    const float* B = (z == 0) ? Wq : (z == 1) ? Wk : Wv;

    const int tid = threadIdx.x;
    const int m0  = blockIdx.y * 128;
    const int n0  = blockIdx.x * 128;
    const int tm  = tid >> 4;
    const int tn  = tid & 15;
    const int lr  = tid >> 2;
    const int lc  = (tid & 3) * 4;

    float acc[8][8];
    #pragma unroll
    for (int i = 0; i < 8; i++)
        #pragma unroll
        for (int j = 0; j < 8; j++) acc[i][j] = 0.0f;

    for (int k0 = 0; k0 < KD; k0 += 16) {
        #pragma unroll
        for (int rr = 0; rr < 2; rr++) {
            int row = lr + rr * 64;
            float4 v = *(const float4*)(A + (size_t)(m0 + row) * KD + k0 + lc);
            As[lc + 0][row] = v.x; As[lc + 1][row] = v.y;
            As[lc + 2][row] = v.z; As[lc + 3][row] = v.w;
        }
        #pragma unroll
        for (int rr = 0; rr < 2; rr++) {
            int row = lr + rr * 64;
            float4 v = *(const float4*)(B + (size_t)(n0 + row) * KD + k0 + lc);
            Bs[lc + 0][row] = v.x; Bs[lc + 1][row] = v.y;
            Bs[lc + 2][row] = v.z; Bs[lc + 3][row] = v.w;
        }
        __syncthreads();
        #pragma unroll
        for (int kk = 0; kk < 16; kk++) {
            float a[8], b[8];
            *(float4*)(a)     = *(const float4*)&As[kk][tm * 8];
            *(float4*)(a + 4) = *(const float4*)&As[kk][tm * 8 + 4];
            *(float4*)(b)     = *(const float4*)&Bs[kk][tn * 8];
            *(float4*)(b + 4) = *(const float4*)&Bs[kk][tn * 8 + 4];
            #pragma unroll
            for (int i = 0; i < 8; i++)
                #pragma unroll
                for (int j = 0; j < 8; j++)
                    acc[i][j] += a[i] * b[j];
        }
        __syncthreads();
    }

    bf16* hi_arr = (z == 0) ? qh : (z == 1) ? kh : vh;
    bf16* lo_arr = (z == 0) ? ql : (z == 1) ? kl : vl;
    const float scale = (z == 0) ? 0.125f : 1.0f;

    if (z < 2) {
        // RoPE epilogue
        #pragma unroll
        for (int i = 0; i < 8; i++) {
            int mrow = m0 + tm * 8 + i;
            int p = pos[mrow];
            const float* cr = cosc + (size_t)p * HALF;
            const float* sr = sinc + (size_t)p * HALF;
            #pragma unroll
            for (int jp = 0; jp < 4; jp++) {
                int n  = n0 + tn * 8 + 2 * jp;
                int dh = n & 63;
                int hh = n >> 6;
                float cc = cr[dh >> 1];
                float ss = sr[dh >> 1];
                float e = acc[i][2 * jp];
                float o = acc[i][2 * jp + 1];
                float re = (e * cc - o * ss) * scale;
                float ro = (e * ss + o * cc) * scale;
                split_store_pair(hi_arr, lo_arr,
                                 ((size_t)hh * SEQ + mrow) * DH + dh, re, ro);
            }
        }
    } else {
        #pragma unroll
        for (int i = 0; i < 8; i++) {
            int mrow = m0 + tm * 8 + i;
            #pragma unroll
            for (int jp = 0; jp < 4; jp++) {
                int n  = n0 + tn * 8 + 2 * jp;
                int dh = n & 63;
                int hh = n >> 6;
                split_store_pair(hi_arr, lo_arr,
                                 ((size_t)hh * SEQ + mrow) * DH + dh,
                                 acc[i][2 * jp], acc[i][2 * jp + 1]);
            }
        }
    }
}

// ---------------------------------------------------------------------------
// Plain fp32 NT GEMM for the output projection (known good from R1).
// ---------------------------------------------------------------------------
__global__ __launch_bounds__(256)
void gemm_out(const float* __restrict__ A, const float* __restrict__ B,
              float* __restrict__ C)
{
    constexpr int KD = 768;
    constexpr int N  = 768;
    __shared__ __align__(16) float As[16][132];
    __shared__ __align__(16) float Bs[16][132];

    const int tid = threadIdx.x;
    const int m0  = blockIdx.y * 128;
    const int n0  = blockIdx.x * 128;
    const int tm  = tid >> 4;
    const int tn  = tid & 15;
    const int lr  = tid >> 2;
    const int lc  = (tid & 3) * 4;

    float acc[8][8];
    #pragma unroll
    for (int i = 0; i < 8; i++)
        #pragma unroll
        for (int j = 0; j < 8; j++) acc[i][j] = 0.0f;

    for (int k0 = 0; k0 < KD; k0 += 16) {
        #pragma unroll
        for (int rr = 0; rr < 2; rr++) {
            int row = lr + rr * 64;
            float4 v = *(const float4*)(A + (size_t)(m0 + row) * KD + k0 + lc);
            As[lc + 0][row] = v.x; As[lc + 1][row] = v.y;
            As[lc + 2][row] = v.z; As[lc + 3][row] = v.w;
        }
        #pragma unroll
        for (int rr = 0; rr < 2; rr++) {
            int row = lr + rr * 64;
            float4 v = *(const float4*)(B + (size_t)(n0 + row) * KD + k0 + lc);
            Bs[lc + 0][row] = v.x; Bs[lc + 1][row] = v.y;
            Bs[lc + 2][row] = v.z; Bs[lc + 3][row] = v.w;
        }
        __syncthreads();
        #pragma unroll
        for (int kk = 0; kk < 16; kk++) {
            float a[8], b[8];
            *(float4*)(a)     = *(const float4*)&As[kk][tm * 8];
            *(float4*)(a + 4) = *(const float4*)&As[kk][tm * 8 + 4];
            *(float4*)(b)     = *(const float4*)&Bs[kk][tn * 8];
            *(float4*)(b + 4) = *(const float4*)&Bs[kk][tn * 8 + 4];
            #pragma unroll
            for (int i = 0; i < 8; i++)
                #pragma unroll
                for (int j = 0; j < 8; j++)
                    acc[i][j] += a[i] * b[j];
        }
        __syncthreads();
    }

    #pragma unroll
    for (int i = 0; i < 8; i++) {
        int mrow = m0 + tm * 8 + i;
        float* dst = C + (size_t)mrow * N + n0 + tn * 8;
        *(float4*)(dst)     = make_float4(acc[i][0], acc[i][1], acc[i][2], acc[i][3]);
        *(float4*)(dst + 4) = make_float4(acc[i][4], acc[i][5], acc[i][6], acc[i][7]);
    }
}

// ---------------------------------------------------------------------------
// Flash attention with bf16 split-mma (hi*hi + hi*lo + lo*hi ~ fp32 accuracy).
// CTA: 128 q rows (8 warps x 16 rows), 64-wide KV tiles, causal.
// smem: K hi/lo + V hi/lo tiles (4 x 8KB), swizzled for ldmatrix.
// Scale (1/8) pre-folded into Q by the projection epilogue.
// ---------------------------------------------------------------------------
__global__ __launch_bounds__(256)
void attn_mma(const bf16* __restrict__ Qh, const bf16* __restrict__ Ql,
              const bf16* __restrict__ Kh, const bf16* __restrict__ Kl,
              const bf16* __restrict__ Vh, const bf16* __restrict__ Vl,
              float* __restrict__ O)
{
    __shared__ __align__(128) uint8_t sm[32768];

    const int h   = blockIdx.y;
    const int qb  = (int)gridDim.x - 1 - (int)blockIdx.x;   // big blocks first
    const int q0  = qb * 128;
    const int tid = threadIdx.x;
    const int wid = tid >> 5;
    const int lane = tid & 31;

    const size_t hoff = (size_t)h * SEQ * DH;
    const uint32_t smbase = (uint32_t)__cvta_generic_to_shared(sm);

    // ---- stage Q hi/lo tiles, pull A-fragments into registers ----
    {
        const uint8_t* qsH = (const uint8_t*)(Qh + hoff + (size_t)q0 * DH);
        const uint8_t* qsL = (const uint8_t*)(Ql + hoff + (size_t)q0 * DH);
        for (int i = tid; i < 1024; i += 256) {
            int row = i >> 3, ch = i & 7;
            uint32_t off = row * 128 + ((ch ^ (row & 7)) << 4);
            *(uint4*)(sm + off)         = *(const uint4*)(qsH + row * 128 + ch * 16);
            *(uint4*)(sm + 16384 + off) = *(const uint4*)(qsL + row * 128 + ch * 16);
        }
    }
    __syncthreads();

    uint32_t qfh[4][4], qfl[4][4];
    {
        int row = wid * 16 + (lane & 7) + ((lane >> 3) & 1) * 8;
        int chs = lane >> 4;
        #pragma unroll
        for (int kt = 0; kt < 4; kt++) {
            int ch = 2 * kt + chs;
            uint32_t off = row * 128 + ((ch ^ (row & 7)) << 4);
            ldsm4(qfh[kt], smbase + off);
            ldsm4(qfl[kt], smbase + 16384 + off);
        }
    }
    __syncthreads();

    float o[8][4];
    #pragma unroll
    for (int i = 0; i < 8; i++)
        #pragma unroll
        for (int j = 0; j < 4; j++) o[i][j] = 0.0f;
    float mr0 = -1e30f, mr1 = -1e30f, lr0 = 0.0f, lr1 = 0.0f;

    const uint8_t* kHp = (const uint8_t*)(Kh + hoff);
    const uint8_t* kLp = (const uint8_t*)(Kl + hoff);
    const uint8_t* vHp = (const uint8_t*)(Vh + hoff);
    const uint8_t* vLp = (const uint8_t*)(Vl + hoff);

    const int ntile = 2 * qb + 2;
    const int rmax  = q0 + wid * 16 + 15;
    const int r0g   = q0 + wid * 16 + (lane >> 2);

    for (int t = 0; t < ntile; t++) {
        const int k0 = t * 64;

        // fill K/V hi/lo tiles
        for (int i = tid; i < 512; i += 256) {
            int row = i >> 3, ch = i & 7;
            uint32_t off = row * 128 + ((ch ^ (row & 7)) << 4);
            size_t g = (size_t)(k0 + row) * 128 + ch * 16;
            *(uint4*)(sm + off)         = *(const uint4*)(kHp + g);
            *(uint4*)(sm +  8192 + off) = *(const uint4*)(kLp + g);
            *(uint4*)(sm + 16384 + off) = *(const uint4*)(vHp + g);
            *(uint4*)(sm + 24576 + off) = *(const uint4*)(vLp + g);
        }
        __syncthreads();

        if (k0 <= rmax) {
            // ---- S = Q K^T (split) ----
            float s[8][4];
            #pragma unroll
            for (int nt = 0; nt < 8; nt++)
                #pragma unroll
                for (int j = 0; j < 4; j++) s[nt][j] = 0.0f;

            #pragma unroll
            for (int nt = 0; nt < 8; nt++) {
                uint32_t bh[8], bl[8];
                int row = nt * 8 + (lane & 7);
                {
                    int ch = lane >> 3;
                    uint32_t off = row * 128 + ((ch ^ (row & 7)) << 4);
                    ldsm4(bh,     smbase + off);
                    ldsm4(bl,     smbase + 8192 + off);
                    int ch2 = 4 + (lane >> 3);
                    uint32_t off2 = row * 128 + ((ch2 ^ (row & 7)) << 4);
                    ldsm4(bh + 4, smbase + off2);
                    ldsm4(bl + 4, smbase + 8192 + off2);
                }
                #pragma unroll
                for (int kt = 0; kt < 4; kt++) {
                    mma16816(s[nt], qfh[kt], bh + 2 * kt);
                    mma16816(s[nt], qfh[kt], bl + 2 * kt);
                    mma16816(s[nt], qfl[kt], bh + 2 * kt);
                }
            }

            // ---- causal mask ----
            if (k0 + 63 > q0 + wid * 16) {
                #pragma unroll
                for (int nt = 0; nt < 8; nt++) {
                    int c0 = k0 + nt * 8 + ((lane & 3) << 1);
                    if (c0     > r0g)     s[nt][0] = -1e30f;
                    if (c0 + 1 > r0g)     s[nt][1] = -1e30f;
                    if (c0     > r0g + 8) s[nt][2] = -1e30f;
                    if (c0 + 1 > r0g + 8) s[nt][3] = -1e30f;
                }
            }

            // ---- online softmax ----
            float mx0 = -1e30f, mx1 = -1e30f;
            #pragma unroll
            for (int nt = 0; nt < 8; nt++) {
                mx0 = fmaxf(mx0, fmaxf(s[nt][0], s[nt][1]));
                mx1 = fmaxf(mx1, fmaxf(s[nt][2], s[nt][3]));
            }
            mx0 = fmaxf(mx0, __shfl_xor_sync(0xffffffffu, mx0, 1));
            mx0 = fmaxf(mx0, __shfl_xor_sync(0xffffffffu, mx0, 2));
            mx1 = fmaxf(mx1, __shfl_xor_sync(0xffffffffu, mx1, 1));
            mx1 = fmaxf(mx1, __shfl_xor_sync(0xffffffffu, mx1, 2));

            float mn0 = fmaxf(mr0, mx0), mn1 = fmaxf(mr1, mx1);
            float c0 = expf(mr0 - mn0), c1 = expf(mr1 - mn1);
            mr0 = mn0; mr1 = mn1;

            float sum0 = 0.0f, sum1 = 0.0f;
            #pragma unroll
            for (int nt = 0; nt < 8; nt++) {
                s[nt][0] = expf(s[nt][0] - mn0);
                s[nt][1] = expf(s[nt][1] - mn0);
                s[nt][2] = expf(s[nt][2] - mn1);
                s[nt][3] = expf(s[nt][3] - mn1);
                sum0 += s[nt][0] + s[nt][1];
                sum1 += s[nt][2] + s[nt][3];
            }
            sum0 += __shfl_xor_sync(0xffffffffu, sum0, 1);
            sum0 += __shfl_xor_sync(0xffffffffu, sum0, 2);
            sum1 += __shfl_xor_sync(0xffffffffu, sum1, 1);
            sum1 += __shfl_xor_sync(0xffffffffu, sum1, 2);
            lr0 = lr0 * c0 + sum0;
            lr1 = lr1 * c1 + sum1;

            #pragma unroll
            for (int dt = 0; dt < 8; dt++) {
                o[dt][0] *= c0; o[dt][1] *= c0;
                o[dt][2] *= c1; o[dt][3] *= c1;
            }

            // ---- P -> A fragments (hi/lo split), no smem round trip ----
            uint32_t pfh[4][4], pfl[4][4];
            #pragma unroll
            for (int kt = 0; kt < 4; kt++) {
                splitpack(s[2*kt][0],   s[2*kt][1],   pfh[kt][0], pfl[kt][0]);
                splitpack(s[2*kt][2],   s[2*kt][3],   pfh[kt][1], pfl[kt][1]);
                splitpack(s[2*kt+1][0], s[2*kt+1][1], pfh[kt][2], pfl[kt][2]);
                splitpack(s[2*kt+1][2], s[2*kt+1][3], pfh[kt][3], pfl[kt][3]);
            }

            // ---- O += P V (split) ----
            #pragma unroll
            for (int dp = 0; dp < 4; dp++) {
                #pragma unroll
                for (int kt = 0; kt < 4; kt++) {
                    uint32_t vh4[4], vl4[4];
                    int vrow = kt * 16 + (lane & 7) + ((lane >> 3) & 1) * 8;
                    int ch = 2 * dp + (lane >> 4);
                    uint32_t off = vrow * 128 + ((ch ^ (vrow & 7)) << 4);
                    ldsm4t(vh4, smbase + 16384 + off);
                    ldsm4t(vl4, smbase + 24576 + off);
                    mma16816(o[2*dp],     pfh[kt], vh4);
                    mma16816(o[2*dp],     pfh[kt], vl4);
                    mma16816(o[2*dp],     pfl[kt], vh4);
                    mma16816(o[2*dp + 1], pfh[kt], vh4 + 2);
                    mma16816(o[2*dp + 1], pfh[kt], vl4 + 2);
                    mma16816(o[2*dp + 1], pfl[kt], vh4 + 2);
                }
            }
        }
        __syncthreads();
    }

    // ---- epilogue: O / l -> [s][768] ----
    float i0 = 1.0f / lr0, i1 = 1.0f / lr1;
    int cb = h * DH + ((lane & 3) << 1);
    #pragma unroll
    for (int dt = 0; dt < 8; dt++) {
        *(float2*)&O[(size_t)r0g * DMODEL + cb + dt * 8] =
            make_float2(o[dt][0] * i0, o[dt][1] * i0);
        *(float2*)&O[(size_t)(r0g + 8) * DMODEL + cb + dt * 8] =
            make_float2(o[dt][2] * i1, o[dt][3] * i1);
    }
}

// ---------------------------------------------------------------------------
// kernel_launch — graph-capturable, allocation-free.
// ---------------------------------------------------------------------------
extern "C" void kernel_launch(void* const* d_in, const int* in_sizes, int n_in,
                              void* d_out, int out_size)
{
    const float* x   = (const float*)d_in[0];
    const float* wq  = (const float*)d_in[1];
    const float* wk  = (const float*)d_in[2];
    const float* wv  = (const float*)d_in[3];
    const float* wo  = (const float*)d_in[4];
    const int*   pos = (const int*)d_in[5];
    float* out = (float*)d_out;

    bf16 *qh, *ql, *kh, *kl, *vh, *vl;
    float *op, *cp, *sp;
    cudaGetSymbolAddress((void**)&qh, g_qh);
    cudaGetSymbolAddress((void**)&ql, g_ql);
    cudaGetSymbolAddress((void**)&kh, g_kh);
    cudaGetSymbolAddress((void**)&kl, g_kl);
    cudaGetSymbolAddress((void**)&vh, g_vh);
    cudaGetSymbolAddress((void**)&vl, g_vl);
    cudaGetSymbolAddress((void**)&op, g_o);
    cudaGetSymbolAddress((void**)&cp, g_cos);
    cudaGetSymbolAddress((void**)&sp, g_sin);

    // 1. RoPE cache
    rope_cache_kernel<<<(SEQ * HALF + 255) / 256, 256>>>(cp, sp);

    // 2. Fused QKV projections with RoPE + bf16 hi/lo split epilogue
    dim3 gq(DMODEL / 128, SEQ / 128, 3);
    gemm_qkv<<<gq, 256>>>(x, wq, wk, wv, qh, ql, kh, kl, vh, vl, pos, cp, sp);

    // 3. Causal flash attention (split-bf16 tensor-core mma)
    attn_mma<<<dim3(SEQ / 128, NH), 256>>>(qh, ql, kh, kl, vh, vl, op);

    // 4. Output projection (fp32 SIMT)
    dim3 gg(DMODEL / 128, SEQ / 128);
    gemm_out<<<gg, 256>>>(op, wo, out);
}

// round 3
// speedup vs baseline: 2.4377x; 1.9574x over previous
#include <cuda_runtime.h>
#include <cuda_bf16.h>
#include <math.h>
#include <stdint.h>

using bf16 = __nv_bfloat16;

constexpr int SEQ    = 4096;
constexpr int DMODEL = 768;
constexpr int NH     = 12;
constexpr int DH     = 64;
constexpr int HALF   = DH / 2;   // 32

// Scratch (device globals; no runtime allocation allowed)
__device__ bf16  g_qh[NH * SEQ * DH];
__device__ bf16  g_ql[NH * SEQ * DH];
__device__ bf16  g_kh[NH * SEQ * DH];
__device__ bf16  g_kl[NH * SEQ * DH];
__device__ bf16  g_vh[NH * SEQ * DH];
__device__ bf16  g_vl[NH * SEQ * DH];
__device__ float g_o[SEQ * DMODEL];
__device__ float g_cos[SEQ * HALF];
__device__ float g_sin[SEQ * HALF];

// ---------------------------------------------------------------------------
// RoPE cos/sin cache
// ---------------------------------------------------------------------------
__global__ void rope_cache_kernel(float* __restrict__ c, float* __restrict__ s)
{
    int i = blockIdx.x * blockDim.x + threadIdx.x;
    if (i >= SEQ * HALF) return;
    int p = i >> 5;
    int k = i & 31;
    float expo = -2.0f * (float)k / (float)DH;
    float invf = powf(10000.0f, expo);
    float ang  = (float)p * invf;
    c[i] = cosf(ang);
    s[i] = sinf(ang);
}

// ---------------------------------------------------------------------------
// bf16 split helpers
// ---------------------------------------------------------------------------
__device__ __forceinline__ void split_store_pair(bf16* __restrict__ hi_arr,
                                                 bf16* __restrict__ lo_arr,
                                                 size_t idx, float a, float b)
{
    __nv_bfloat162 h = __floats2bfloat162_rn(a, b);
    float ha = __bfloat162float(h.x);
    float hb = __bfloat162float(h.y);
    __nv_bfloat162 l = __floats2bfloat162_rn(a - ha, b - hb);
    *reinterpret_cast<__nv_bfloat162*>(hi_arr + idx) = h;
    *reinterpret_cast<__nv_bfloat162*>(lo_arr + idx) = l;
}

__device__ __forceinline__ void splitpack(float a, float b,
                                          uint32_t& hi, uint32_t& lo)
{
    __nv_bfloat162 h = __floats2bfloat162_rn(a, b);
    float ha = __bfloat162float(h.x);
    float hb = __bfloat162float(h.y);
    __nv_bfloat162 l = __floats2bfloat162_rn(a - ha, b - hb);
    hi = *reinterpret_cast<uint32_t*>(&h);
    lo = *reinterpret_cast<uint32_t*>(&l);
}

// 8 fp32 -> 16B hi + 16B lo bf16
__device__ __forceinline__ void cvt8_split(const float4& p0, const float4& p1,
                                           uint4& hi, uint4& lo)
{
    uint32_t h0, l0, h1, l1, h2, l2, h3, l3;
    splitpack(p0.x, p0.y, h0, l0);
    splitpack(p0.z, p0.w, h1, l1);
    splitpack(p1.x, p1.y, h2, l2);
    splitpack(p1.z, p1.w, h3, l3);
    hi = make_uint4(h0, h1, h2, h3);
    lo = make_uint4(l0, l1, l2, l3);
}

// ---------------------------------------------------------------------------
// mma / ldmatrix wrappers
// ---------------------------------------------------------------------------
__device__ __forceinline__ void ldsm4(uint32_t* r, uint32_t addr)
{
    asm volatile("ldmatrix.sync.aligned.m8n8.x4.shared.b16 {%0,%1,%2,%3}, [%4];"
        : "=r"(r[0]), "=r"(r[1]), "=r"(r[2]), "=r"(r[3]) : "r"(addr));
}
__device__ __forceinline__ void ldsm2(uint32_t* r, uint32_t addr)
{
    asm volatile("ldmatrix.sync.aligned.m8n8.x2.shared.b16 {%0,%1}, [%2];"
        : "=r"(r[0]), "=r"(r[1]) : "r"(addr));
}
__device__ __forceinline__ void ldsm4t(uint32_t* r, uint32_t addr)
{
    asm volatile("ldmatrix.sync.aligned.m8n8.x4.trans.shared.b16 {%0,%1,%2,%3}, [%4];"
        : "=r"(r[0]), "=r"(r[1]), "=r"(r[2]), "=r"(r[3]) : "r"(addr));
}
__device__ __forceinline__ void mma16816(float* d, const uint32_t* a, const uint32_t* b)
{
    asm volatile(
        "mma.sync.aligned.m16n8k16.row.col.f32.bf16.bf16.f32 "
        "{%0,%1,%2,%3}, {%4,%5,%6,%7}, {%8,%9}, {%0,%1,%2,%3};"
        : "+f"(d[0]), "+f"(d[1]), "+f"(d[2]), "+f"(d[3])
        : "r"(a[0]), "r"(a[1]), "r"(a[2]), "r"(a[3]), "r"(b[0]), "r"(b[1]));
}

// ---------------------------------------------------------------------------
// Split-bf16 tensor-core NT GEMM: C = A(M,768) @ B(768,768)^T
// fp32 inputs converted to hi/lo bf16 on the fly; 3-term split MMA.
// Tile 128x128x32, 8 warps (4x2), warp tile 32x64, mma m16n8k16.
// MODE 0: plain fp32 store to Cout
// MODE 1: QKV fused (blockIdx.z selects W & output); RoPE for z<2;
//         bf16 hi/lo split-store scattered to [h][s][64].
// ---------------------------------------------------------------------------
template<int MODE>
__global__ __launch_bounds__(256)
void gemm_mma(const float* __restrict__ A,
              const float* __restrict__ W0, const float* __restrict__ W1,
              const float* __restrict__ W2,
              float* __restrict__ Cout,
              bf16* __restrict__ qh, bf16* __restrict__ ql,
              bf16* __restrict__ kh, bf16* __restrict__ kl,
              bf16* __restrict__ vh, bf16* __restrict__ vl,
              const int* __restrict__ pos,
              const float* __restrict__ cosc, const float* __restrict__ sinc)
{
    constexpr int KD = 768;
    // smem: Ah(8K) Al(8K) Bh(8K) Bl(8K), bf16 [128 rows][32 k], swizzled 16B chunks
    __shared__ __align__(128) uint8_t sm[32768];
    const uint32_t smb = (uint32_t)__cvta_generic_to_shared(sm);

    const int z = (MODE == 1) ? blockIdx.z : 0;
    const float* B = (MODE == 0) ? W0 : (z == 0) ? W0 : (z == 1) ? W1 : W2;

    const int tid  = threadIdx.x;
    const int wid  = tid >> 5;
    const int lane = tid & 31;
    const int m0   = blockIdx.y * 128;
    const int n0   = blockIdx.x * 128;
    const int wm   = wid >> 1;       // 0..3
    const int wn   = wid & 1;        // 0..1

    // loader mapping: thread -> (row, 16-float half-row)
    const int lrow = tid >> 1;            // 0..127
    const int lkb  = (tid & 1) * 16;      // fp32 offset within 32-chunk

    float acc[2][8][4];
    #pragma unroll
    for (int m = 0; m < 2; m++)
        #pragma unroll
        for (int n = 0; n < 8; n++)
            #pragma unroll
            for (int j = 0; j < 4; j++) acc[m][n][j] = 0.0f;

    auto smoff = [](int row, int o) -> uint32_t {
        return (uint32_t)(row * 64 + ((o ^ (row & 3)) << 4));
    };

    // prefetch registers
    float4 pa[4], pb[4];
    {
        const float* ap = A + (size_t)(m0 + lrow) * KD + lkb;
        const float* bp = B + (size_t)(n0 + lrow) * KD + lkb;
        #pragma unroll
        for (int i = 0; i < 4; i++) {
            pa[i] = *(const float4*)(ap + 4 * i);
            pb[i] = *(const float4*)(bp + 4 * i);
        }
    }

    for (int k0 = 0; k0 < KD; k0 += 32) {
        // store prefetched chunk (convert fp32 -> hi/lo bf16)
        #pragma unroll
        for (int i = 0; i < 2; i++) {
            int o = (lkb >> 3) + i;
            uint4 hi, lo;
            cvt8_split(pa[2 * i], pa[2 * i + 1], hi, lo);
            *(uint4*)(sm +         smoff(lrow, o)) = hi;
            *(uint4*)(sm +  8192 + smoff(lrow, o)) = lo;
            cvt8_split(pb[2 * i], pb[2 * i + 1], hi, lo);
            *(uint4*)(sm + 16384 + smoff(lrow, o)) = hi;
            *(uint4*)(sm + 24576 + smoff(lrow, o)) = lo;
        }
        __syncthreads();

        // prefetch next chunk
        if (k0 + 32 < KD) {
            const float* ap = A + (size_t)(m0 + lrow) * KD + k0 + 32 + lkb;
            const float* bp = B + (size_t)(n0 + lrow) * KD + k0 + 32 + lkb;
            #pragma unroll
            for (int i = 0; i < 4; i++) {
                pa[i] = *(const float4*)(ap + 4 * i);
                pb[i] = *(const float4*)(bp + 4 * i);
            }
        }

        // MMA over the 32-k chunk
        #pragma unroll
        for (int kt = 0; kt < 2; kt++) {
            uint32_t ah[2][4], al[2][4];
            #pragma unroll
            for (int m = 0; m < 2; m++) {
                int row = wm * 32 + m * 16 + (lane & 7) + ((lane >> 3) & 1) * 8;
                int ch  = 2 * kt + (lane >> 4);
                uint32_t off = smoff(row, ch);
                ldsm4(ah[m], smb + off);
                ldsm4(al[m], smb + 8192 + off);
            }
            #pragma unroll
            for (int nt = 0; nt < 8; nt++) {
                uint32_t bh[2], bl[2];
                int row = wn * 64 + nt * 8 + (lane & 7);
                int ch  = 2 * kt + ((lane >> 3) & 1);
                uint32_t off = smoff(row, ch);
                ldsm2(bh, smb + 16384 + off);
                ldsm2(bl, smb + 24576 + off);
                #pragma unroll
                for (int m = 0; m < 2; m++) {
                    mma16816(acc[m][nt], ah[m], bh);
                    mma16816(acc[m][nt], ah[m], bl);
                    mma16816(acc[m][nt], al[m], bh);
                }
            }
        }
        __syncthreads();
    }

    // ---- epilogue ----
    const int rbase = m0 + wm * 32 + (lane >> 2);
    const int cbase = n0 + wn * 64 + (lane & 3) * 2;

    if (MODE == 0) {
        #pragma unroll
        for (int m = 0; m < 2; m++)
            #pragma unroll
            for (int nt = 0; nt < 8; nt++) {
                const float* v = acc[m][nt];
                int r = rbase + m * 16;
                int c = cbase + nt * 8;
                *(float2*)&Cout[(size_t)r * DMODEL + c]       = make_float2(v[0], v[1]);
                *(float2*)&Cout[(size_t)(r + 8) * DMODEL + c] = make_float2(v[2], v[3]);
            }
    } else {
        bf16* hi_arr = (z == 0) ? qh : (z == 1) ? kh : vh;
        bf16* lo_arr = (z == 0) ? ql : (z == 1) ? kl : vl;
        const float scale = (z == 0) ? 0.125f : 1.0f;

        #pragma unroll
        for (int m = 0; m < 2; m++) {
            int r = rbase + m * 16;
            if (z < 2) {
                int p0 = pos[r], p1 = pos[r + 8];
                const float* cr0 = cosc + (size_t)p0 * HALF;
                const float* sr0 = sinc + (size_t)p0 * HALF;
                const float* cr1 = cosc + (size_t)p1 * HALF;
                const float* sr1 = sinc + (size_t)p1 * HALF;
                #pragma unroll
                for (int nt = 0; nt < 8; nt++) {
                    const float* v = acc[m][nt];
                    int c  = cbase + nt * 8;
                    int dh = c & 63;
                    int hh = c >> 6;
                    float cc = cr0[dh >> 1], ss = sr0[dh >> 1];
                    float re = (v[0] * cc - v[1] * ss) * scale;
                    float ro = (v[0] * ss + v[1] * cc) * scale;
                    split_store_pair(hi_arr, lo_arr,
                                     ((size_t)hh * SEQ + r) * DH + dh, re, ro);
                    cc = cr1[dh >> 1]; ss = sr1[dh >> 1];
                    re = (v[2] * cc - v[3] * ss) * scale;
                    ro = (v[2] * ss + v[3] * cc) * scale;
                    split_store_pair(hi_arr, lo_arr,
                                     ((size_t)hh * SEQ + r + 8) * DH + dh, re, ro);
                }
            } else {
                #pragma unroll
                for (int nt = 0; nt < 8; nt++) {
                    const float* v = acc[m][nt];
                    int c  = cbase + nt * 8;
                    int dh = c & 63;
                    int hh = c >> 6;
                    split_store_pair(hi_arr, lo_arr,
                                     ((size_t)hh * SEQ + r) * DH + dh, v[0], v[1]);
                    split_store_pair(hi_arr, lo_arr,
                                     ((size_t)hh * SEQ + r + 8) * DH + dh, v[2], v[3]);
                }
            }
        }
    }
}

// ---------------------------------------------------------------------------
// Flash attention with bf16 split-mma (unchanged from R2 — passed, ~310us).
// ---------------------------------------------------------------------------
__global__ __launch_bounds__(256)
void attn_mma(const bf16* __restrict__ Qh, const bf16* __restrict__ Ql,
              const bf16* __restrict__ Kh, const bf16* __restrict__ Kl,
              const bf16* __restrict__ Vh, const bf16* __restrict__ Vl,
              float* __restrict__ O)
{
    __shared__ __align__(128) uint8_t sm[32768];

    const int h   = blockIdx.y;
    const int qb  = (int)gridDim.x - 1 - (int)blockIdx.x;   // big blocks first
    const int q0  = qb * 128;
    const int tid = threadIdx.x;
    const int wid = tid >> 5;
    const int lane = tid & 31;

    const size_t hoff = (size_t)h * SEQ * DH;
    const uint32_t smbase = (uint32_t)__cvta_generic_to_shared(sm);

    {
        const uint8_t* qsH = (const uint8_t*)(Qh + hoff + (size_t)q0 * DH);
        const uint8_t* qsL = (const uint8_t*)(Ql + hoff + (size_t)q0 * DH);
        for (int i = tid; i < 1024; i += 256) {
            int row = i >> 3, ch = i & 7;
            uint32_t off = row * 128 + ((ch ^ (row & 7)) << 4);
            *(uint4*)(sm + off)         = *(const uint4*)(qsH + row * 128 + ch * 16);
            *(uint4*)(sm + 16384 + off) = *(const uint4*)(qsL + row * 128 + ch * 16);
        }
    }
    __syncthreads();

    uint32_t qfh[4][4], qfl[4][4];
    {
        int row = wid * 16 + (lane & 7) + ((lane >> 3) & 1) * 8;
        int chs = lane >> 4;
        #pragma unroll
        for (int kt = 0; kt < 4; kt++) {
            int ch = 2 * kt + chs;
            uint32_t off = row * 128 + ((ch ^ (row & 7)) << 4);
            ldsm4(qfh[kt], smbase + off);
            ldsm4(qfl[kt], smbase + 16384 + off);
        }
    }
    __syncthreads();

    float o[8][4];
    #pragma unroll
    for (int i = 0; i < 8; i++)
        #pragma unroll
        for (int j = 0; j < 4; j++) o[i][j] = 0.0f;
    float mr0 = -1e30f, mr1 = -1e30f, lr0 = 0.0f, lr1 = 0.0f;

    const uint8_t* kHp = (const uint8_t*)(Kh + hoff);
    const uint8_t* kLp = (const uint8_t*)(Kl + hoff);
    const uint8_t* vHp = (const uint8_t*)(Vh + hoff);
    const uint8_t* vLp = (const uint8_t*)(Vl + hoff);

    const int ntile = 2 * qb + 2;
    const int rmax  = q0 + wid * 16 + 15;
    const int r0g   = q0 + wid * 16 + (lane >> 2);

    for (int t = 0; t < ntile; t++) {
        const int k0 = t * 64;

        for (int i = tid; i < 512; i += 256) {
            int row = i >> 3, ch = i & 7;
            uint32_t off = row * 128 + ((ch ^ (row & 7)) << 4);
            size_t g = (size_t)(k0 + row) * 128 + ch * 16;
            *(uint4*)(sm + off)         = *(const uint4*)(kHp + g);
            *(uint4*)(sm +  8192 + off) = *(const uint4*)(kLp + g);
            *(uint4*)(sm + 16384 + off) = *(const uint4*)(vHp + g);
            *(uint4*)(sm + 24576 + off) = *(const uint4*)(vLp + g);
        }
        __syncthreads();

        if (k0 <= rmax) {
            float s[8][4];
            #pragma unroll
            for (int nt = 0; nt < 8; nt++)
                #pragma unroll
                for (int j = 0; j < 4; j++) s[nt][j] = 0.0f;

            #pragma unroll
            for (int nt = 0; nt < 8; nt++) {
                uint32_t bh[8], bl[8];
                int row = nt * 8 + (lane & 7);
                {
                    int ch = lane >> 3;
                    uint32_t off = row * 128 + ((ch ^ (row & 7)) << 4);
                    ldsm4(bh,     smbase + off);
                    ldsm4(bl,     smbase + 8192 + off);
                    int ch2 = 4 + (lane >> 3);
                    uint32_t off2 = row * 128 + ((ch2 ^ (row & 7)) << 4);
                    ldsm4(bh + 4, smbase + off2);
                    ldsm4(bl + 4, smbase + 8192 + off2);
                }
                #pragma unroll
                for (int kt = 0; kt < 4; kt++) {
                    mma16816(s[nt], qfh[kt], bh + 2 * kt);
                    mma16816(s[nt], qfh[kt], bl + 2 * kt);
                    mma16816(s[nt], qfl[kt], bh + 2 * kt);
                }
            }

            if (k0 + 63 > q0 + wid * 16) {
                #pragma unroll
                for (int nt = 0; nt < 8; nt++) {
                    int c0 = k0 + nt * 8 + ((lane & 3) << 1);
                    if (c0     > r0g)     s[nt][0] = -1e30f;
                    if (c0 + 1 > r0g)     s[nt][1] = -1e30f;
                    if (c0     > r0g + 8) s[nt][2] = -1e30f;
                    if (c0 + 1 > r0g + 8) s[nt][3] = -1e30f;
                }
            }

            float mx0 = -1e30f, mx1 = -1e30f;
            #pragma unroll
            for (int nt = 0; nt < 8; nt++) {
                mx0 = fmaxf(mx0, fmaxf(s[nt][0], s[nt][1]));
                mx1 = fmaxf(mx1, fmaxf(s[nt][2], s[nt][3]));
            }
            mx0 = fmaxf(mx0, __shfl_xor_sync(0xffffffffu, mx0, 1));
            mx0 = fmaxf(mx0, __shfl_xor_sync(0xffffffffu, mx0, 2));
            mx1 = fmaxf(mx1, __shfl_xor_sync(0xffffffffu, mx1, 1));
            mx1 = fmaxf(mx1, __shfl_xor_sync(0xffffffffu, mx1, 2));

            float mn0 = fmaxf(mr0, mx0), mn1 = fmaxf(mr1, mx1);
            float c0 = expf(mr0 - mn0), c1 = expf(mr1 - mn1);
            mr0 = mn0; mr1 = mn1;

            float sum0 = 0.0f, sum1 = 0.0f;
            #pragma unroll
            for (int nt = 0; nt < 8; nt++) {
                s[nt][0] = expf(s[nt][0] - mn0);
                s[nt][1] = expf(s[nt][1] - mn0);
                s[nt][2] = expf(s[nt][2] - mn1);
                s[nt][3] = expf(s[nt][3] - mn1);
                sum0 += s[nt][0] + s[nt][1];
                sum1 += s[nt][2] + s[nt][3];
            }
            sum0 += __shfl_xor_sync(0xffffffffu, sum0, 1);
            sum0 += __shfl_xor_sync(0xffffffffu, sum0, 2);
            sum1 += __shfl_xor_sync(0xffffffffu, sum1, 1);
            sum1 += __shfl_xor_sync(0xffffffffu, sum1, 2);
            lr0 = lr0 * c0 + sum0;
            lr1 = lr1 * c1 + sum1;

            #pragma unroll
            for (int dt = 0; dt < 8; dt++) {
                o[dt][0] *= c0; o[dt][1] *= c0;
                o[dt][2] *= c1; o[dt][3] *= c1;
            }

            uint32_t pfh[4][4], pfl[4][4];
            #pragma unroll
            for (int kt = 0; kt < 4; kt++) {
                splitpack(s[2*kt][0],   s[2*kt][1],   pfh[kt][0], pfl[kt][0]);
                splitpack(s[2*kt][2],   s[2*kt][3],   pfh[kt][1], pfl[kt][1]);
                splitpack(s[2*kt+1][0], s[2*kt+1][1], pfh[kt][2], pfl[kt][2]);
                splitpack(s[2*kt+1][2], s[2*kt+1][3], pfh[kt][3], pfl[kt][3]);
            }

            #pragma unroll
            for (int dp = 0; dp < 4; dp++) {
                #pragma unroll
                for (int kt = 0; kt < 4; kt++) {
                    uint32_t vh4[4], vl4[4];
                    int vrow = kt * 16 + (lane & 7) + ((lane >> 3) & 1) * 8;
                    int ch = 2 * dp + (lane >> 4);
                    uint32_t off = vrow * 128 + ((ch ^ (vrow & 7)) << 4);
                    ldsm4t(vh4, smbase + 16384 + off);
                    ldsm4t(vl4, smbase + 24576 + off);
                    mma16816(o[2*dp],     pfh[kt], vh4);
                    mma16816(o[2*dp],     pfh[kt], vl4);
                    mma16816(o[2*dp],     pfl[kt], vh4);
                    mma16816(o[2*dp + 1], pfh[kt], vh4 + 2);
                    mma16816(o[2*dp + 1], pfh[kt], vl4 + 2);
                    mma16816(o[2*dp + 1], pfl[kt], vh4 + 2);
                }
            }
        }
        __syncthreads();
    }

    float i0 = 1.0f / lr0, i1 = 1.0f / lr1;
    int cb = h * DH + ((lane & 3) << 1);
    #pragma unroll
    for (int dt = 0; dt < 8; dt++) {
        *(float2*)&O[(size_t)r0g * DMODEL + cb + dt * 8] =
            make_float2(o[dt][0] * i0, o[dt][1] * i0);
        *(float2*)&O[(size_t)(r0g + 8) * DMODEL + cb + dt * 8] =
            make_float2(o[dt][2] * i1, o[dt][3] * i1);
    }
}

// ---------------------------------------------------------------------------
// kernel_launch — graph-capturable, allocation-free.
// ---------------------------------------------------------------------------
extern "C" void kernel_launch(void* const* d_in, const int* in_sizes, int n_in,
                              void* d_out, int out_size)
{
    const float* x   = (const float*)d_in[0];
    const float* wq  = (const float*)d_in[1];
    const float* wk  = (const float*)d_in[2];
    const float* wv  = (const float*)d_in[3];
    const float* wo  = (const float*)d_in[4];
    const int*   pos = (const int*)d_in[5];
    float* out = (float*)d_out;

    bf16 *qh, *ql, *kh, *kl, *vh, *vl;
    float *op, *cp, *sp;
    cudaGetSymbolAddress((void**)&qh, g_qh);
    cudaGetSymbolAddress((void**)&ql, g_ql);
    cudaGetSymbolAddress((void**)&kh, g_kh);
    cudaGetSymbolAddress((void**)&kl, g_kl);
    cudaGetSymbolAddress((void**)&vh, g_vh);
    cudaGetSymbolAddress((void**)&vl, g_vl);
    cudaGetSymbolAddress((void**)&op, g_o);
    cudaGetSymbolAddress((void**)&cp, g_cos);
    cudaGetSymbolAddress((void**)&sp, g_sin);

    // 1. RoPE cache
    rope_cache_kernel<<<(SEQ * HALF + 255) / 256, 256>>>(cp, sp);

    // 2. Fused QKV projections (split-bf16 tensor cores, RoPE epilogue)
    dim3 gq(DMODEL / 128, SEQ / 128, 3);
    gemm_mma<1><<<gq, 256>>>(x, wq, wk, wv, nullptr,
                             qh, ql, kh, kl, vh, vl, pos, cp, sp);

    // 3. Causal flash attention (split-bf16 tensor-core mma)
    attn_mma<<<dim3(SEQ / 128, NH), 256>>>(qh, ql, kh, kl, vh, vl, op);

    // 4. Output projection (split-bf16 tensor cores, fp32 store)
    dim3 gg(DMODEL / 128, SEQ / 128, 1);
    gemm_mma<0><<<gg, 256>>>(op, wo, nullptr, nullptr, out,
                             nullptr, nullptr, nullptr, nullptr, nullptr, nullptr,
                             nullptr, nullptr, nullptr);
}

// round 4
// speedup vs baseline: 2.9359x; 1.2044x over previous
#include <cuda_runtime.h>
#include <cuda_bf16.h>
#include <math.h>
#include <stdint.h>

using bf16 = __nv_bfloat16;

constexpr int SEQ    = 4096;
constexpr int DMODEL = 768;
constexpr int NH     = 12;
constexpr int DH     = 64;
constexpr int HALF   = DH / 2;   // 32

// Scratch (device globals; no runtime allocation allowed)
__device__ bf16  g_qh[NH * SEQ * DH];
__device__ bf16  g_ql[NH * SEQ * DH];
__device__ bf16  g_kh[NH * SEQ * DH];
__device__ bf16  g_kl[NH * SEQ * DH];
__device__ bf16  g_vh[NH * SEQ * DH];
__device__ bf16  g_vl[NH * SEQ * DH];
__device__ float g_o[SEQ * DMODEL];
__device__ float g_cos[SEQ * HALF];
__device__ float g_sin[SEQ * HALF];

// ---------------------------------------------------------------------------
// RoPE cos/sin cache
// ---------------------------------------------------------------------------
__global__ void rope_cache_kernel(float* __restrict__ c, float* __restrict__ s)
{
    int i = blockIdx.x * blockDim.x + threadIdx.x;
    if (i >= SEQ * HALF) return;
    int p = i >> 5;
    int k = i & 31;
    float expo = -2.0f * (float)k / (float)DH;
    float invf = powf(10000.0f, expo);
    float ang  = (float)p * invf;
    c[i] = cosf(ang);
    s[i] = sinf(ang);
}

// ---------------------------------------------------------------------------
// bf16 split helpers
// ---------------------------------------------------------------------------
__device__ __forceinline__ void split_store_pair(bf16* __restrict__ hi_arr,
                                                 bf16* __restrict__ lo_arr,
                                                 size_t idx, float a, float b)
{
    __nv_bfloat162 h = __floats2bfloat162_rn(a, b);
    float ha = __bfloat162float(h.x);
    float hb = __bfloat162float(h.y);
    __nv_bfloat162 l = __floats2bfloat162_rn(a - ha, b - hb);
    *reinterpret_cast<__nv_bfloat162*>(hi_arr + idx) = h;
    *reinterpret_cast<__nv_bfloat162*>(lo_arr + idx) = l;
}

__device__ __forceinline__ void splitpack(float a, float b,
                                          uint32_t& hi, uint32_t& lo)
{
    __nv_bfloat162 h = __floats2bfloat162_rn(a, b);
    float ha = __bfloat162float(h.x);
    float hb = __bfloat162float(h.y);
    __nv_bfloat162 l = __floats2bfloat162_rn(a - ha, b - hb);
    hi = *reinterpret_cast<uint32_t*>(&h);
    lo = *reinterpret_cast<uint32_t*>(&l);
}

__device__ __forceinline__ void cvt8_split(const float4& p0, const float4& p1,
                                           uint4& hi, uint4& lo)
{
    uint32_t h0, l0, h1, l1, h2, l2, h3, l3;
    splitpack(p0.x, p0.y, h0, l0);
    splitpack(p0.z, p0.w, h1, l1);
    splitpack(p1.x, p1.y, h2, l2);
    splitpack(p1.z, p1.w, h3, l3);
    hi = make_uint4(h0, h1, h2, h3);
    lo = make_uint4(l0, l1, l2, l3);
}

// ---------------------------------------------------------------------------
// mma / ldmatrix / cp.async wrappers
// ---------------------------------------------------------------------------
__device__ __forceinline__ void ldsm4(uint32_t* r, uint32_t addr)
{
    asm volatile("ldmatrix.sync.aligned.m8n8.x4.shared.b16 {%0,%1,%2,%3}, [%4];"
        : "=r"(r[0]), "=r"(r[1]), "=r"(r[2]), "=r"(r[3]) : "r"(addr));
}
__device__ __forceinline__ void ldsm2(uint32_t* r, uint32_t addr)
{
    asm volatile("ldmatrix.sync.aligned.m8n8.x2.shared.b16 {%0,%1}, [%2];"
        : "=r"(r[0]), "=r"(r[1]) : "r"(addr));
}
__device__ __forceinline__ void ldsm4t(uint32_t* r, uint32_t addr)
{
    asm volatile("ldmatrix.sync.aligned.m8n8.x4.trans.shared.b16 {%0,%1,%2,%3}, [%4];"
        : "=r"(r[0]), "=r"(r[1]), "=r"(r[2]), "=r"(r[3]) : "r"(addr));
}
__device__ __forceinline__ void mma16816(float* d, const uint32_t* a, const uint32_t* b)
{
    asm volatile(
        "mma.sync.aligned.m16n8k16.row.col.f32.bf16.bf16.f32 "
        "{%0,%1,%2,%3}, {%4,%5,%6,%7}, {%8,%9}, {%0,%1,%2,%3};"
        : "+f"(d[0]), "+f"(d[1]), "+f"(d[2]), "+f"(d[3])
        : "r"(a[0]), "r"(a[1]), "r"(a[2]), "r"(a[3]), "r"(b[0]), "r"(b[1]));
}
__device__ __forceinline__ void cp16(uint32_t dst, const void* src)
{
    asm volatile("cp.async.cg.shared.global [%0], [%1], 16;"
        :: "r"(dst), "l"(src));
}
#define CP_COMMIT() asm volatile("cp.async.commit_group;")
#define CP_WAIT(n)  asm volatile("cp.async.wait_group %0;" :: "n"(n))

// ---------------------------------------------------------------------------
// Split-bf16 tensor-core NT GEMM, double-buffered smem.
// Tile 128x128x32, 8 warps, warp tile 32x64, mma m16n8k16, 3-term split.
// MODE 0: plain fp32 store. MODE 1: QKV fused + RoPE + split-store scatter.
// Dynamic smem: 2 stages x 32KB (Ah|Al|Bh|Bl, each 8KB, swizzled).
// ---------------------------------------------------------------------------
template<int MODE>
__global__ __launch_bounds__(256)
void gemm_mma(const float* __restrict__ A,
              const float* __restrict__ W0, const float* __restrict__ W1,
              const float* __restrict__ W2,
              float* __restrict__ Cout,
              bf16* __restrict__ qh, bf16* __restrict__ ql,
              bf16* __restrict__ kh, bf16* __restrict__ kl,
              bf16* __restrict__ vh, bf16* __restrict__ vl,
              const int* __restrict__ pos,
              const float* __restrict__ cosc, const float* __restrict__ sinc)
{
    constexpr int KD = 768;
    constexpr int NCHUNK = KD / 32;   // 24
    extern __shared__ __align__(128) uint8_t sm[];
    const uint32_t smb = (uint32_t)__cvta_generic_to_shared(sm);

    const int z = (MODE == 1) ? blockIdx.z : 0;
    const float* B = (MODE == 0) ? W0 : (z == 0) ? W0 : (z == 1) ? W1 : W2;

    const int tid  = threadIdx.x;
    const int wid  = tid >> 5;
    const int lane = tid & 31;
    const int m0   = blockIdx.y * 128;
    const int n0   = blockIdx.x * 128;
    const int wm   = wid >> 1;
    const int wn   = wid & 1;

    const int lrow = tid >> 1;
    const int lkb  = (tid & 1) * 16;

    float acc[2][8][4];
    #pragma unroll
    for (int m = 0; m < 2; m++)
        #pragma unroll
        for (int n = 0; n < 8; n++)
            #pragma unroll
            for (int j = 0; j < 4; j++) acc[m][n][j] = 0.0f;

    auto smoff = [](int row, int o) -> uint32_t {
        return (uint32_t)(row * 64 + ((o ^ (row & 3)) << 4));
    };

    float4 pa[4], pb[4];
    auto load_chunk = [&](int k0) {
        const float* ap = A + (size_t)(m0 + lrow) * KD + k0 + lkb;
        const float* bp = B + (size_t)(n0 + lrow) * KD + k0 + lkb;
        #pragma unroll
        for (int i = 0; i < 4; i++) {
            pa[i] = *(const float4*)(ap + 4 * i);
            pb[i] = *(const float4*)(bp + 4 * i);
        }
    };
    auto store_chunk = [&](int stage) {
        uint32_t sb = stage * 32768;
        #pragma unroll
        for (int i = 0; i < 2; i++) {
            int o = (lkb >> 3) + i;
            uint4 hi, lo;
            cvt8_split(pa[2 * i], pa[2 * i + 1], hi, lo);
            *(uint4*)(sm + sb +         smoff(lrow, o)) = hi;
            *(uint4*)(sm + sb +  8192 + smoff(lrow, o)) = lo;
            cvt8_split(pb[2 * i], pb[2 * i + 1], hi, lo);
            *(uint4*)(sm + sb + 16384 + smoff(lrow, o)) = hi;
            *(uint4*)(sm + sb + 24576 + smoff(lrow, o)) = lo;
        }
    };

    load_chunk(0);
    store_chunk(0);
    __syncthreads();

    int cur = 0;
    for (int c = 0; c < NCHUNK; c++) {
        if (c + 1 < NCHUNK) load_chunk((c + 1) * 32);

        const uint32_t sb = smb + cur * 32768;
        #pragma unroll
        for (int kt = 0; kt < 2; kt++) {
            uint32_t ah[2][4], al[2][4];
            #pragma unroll
            for (int m = 0; m < 2; m++) {
                int row = wm * 32 + m * 16 + (lane & 7) + ((lane >> 3) & 1) * 8;
                int ch  = 2 * kt + (lane >> 4);
                uint32_t off = smoff(row, ch);
                ldsm4(ah[m], sb + off);
                ldsm4(al[m], sb + 8192 + off);
            }
            #pragma unroll
            for (int nt = 0; nt < 8; nt++) {
                uint32_t bh[2], bl[2];
                int row = wn * 64 + nt * 8 + (lane & 7);
                int ch  = 2 * kt + ((lane >> 3) & 1);
                uint32_t off = smoff(row, ch);
                ldsm2(bh, sb + 16384 + off);
                ldsm2(bl, sb + 24576 + off);
                #pragma unroll
                for (int m = 0; m < 2; m++) {
                    mma16816(acc[m][nt], ah[m], bh);
                    mma16816(acc[m][nt], ah[m], bl);
                    mma16816(acc[m][nt], al[m], bh);
                }
            }
        }

        if (c + 1 < NCHUNK) store_chunk(cur ^ 1);
        __syncthreads();
        cur ^= 1;
    }

    // ---- epilogue ----
    const int rbase = m0 + wm * 32 + (lane >> 2);
    const int cbase = n0 + wn * 64 + (lane & 3) * 2;

    if (MODE == 0) {
        #pragma unroll
        for (int m = 0; m < 2; m++)
            #pragma unroll
            for (int nt = 0; nt < 8; nt++) {
                const float* v = acc[m][nt];
                int r = rbase + m * 16;
                int c = cbase + nt * 8;
                *(float2*)&Cout[(size_t)r * DMODEL + c]       = make_float2(v[0], v[1]);
                *(float2*)&Cout[(size_t)(r + 8) * DMODEL + c] = make_float2(v[2], v[3]);
            }
    } else {
        bf16* hi_arr = (z == 0) ? qh : (z == 1) ? kh : vh;
        bf16* lo_arr = (z == 0) ? ql : (z == 1) ? kl : vl;
        const float scale = (z == 0) ? 0.125f : 1.0f;

        #pragma unroll
        for (int m = 0; m < 2; m++) {
            int r = rbase + m * 16;
            if (z < 2) {
                int p0 = pos[r], p1 = pos[r + 8];
                const float* cr0 = cosc + (size_t)p0 * HALF;
                const float* sr0 = sinc + (size_t)p0 * HALF;
                const float* cr1 = cosc + (size_t)p1 * HALF;
                const float* sr1 = sinc + (size_t)p1 * HALF;
                #pragma unroll
                for (int nt = 0; nt < 8; nt++) {
                    const float* v = acc[m][nt];
                    int c  = cbase + nt * 8;
                    int dh = c & 63;
                    int hh = c >> 6;
                    float cc = cr0[dh >> 1], ss = sr0[dh >> 1];
                    float re = (v[0] * cc - v[1] * ss) * scale;
                    float ro = (v[0] * ss + v[1] * cc) * scale;
                    split_store_pair(hi_arr, lo_arr,
                                     ((size_t)hh * SEQ + r) * DH + dh, re, ro);
                    cc = cr1[dh >> 1]; ss = sr1[dh >> 1];
                    re = (v[2] * cc - v[3] * ss) * scale;
                    ro = (v[2] * ss + v[3] * cc) * scale;
                    split_store_pair(hi_arr, lo_arr,
                                     ((size_t)hh * SEQ + r + 8) * DH + dh, re, ro);
                }
            } else {
                #pragma unroll
                for (int nt = 0; nt < 8; nt++) {
                    const float* v = acc[m][nt];
                    int c  = cbase + nt * 8;
                    int dh = c & 63;
                    int hh = c >> 6;
                    split_store_pair(hi_arr, lo_arr,
                                     ((size_t)hh * SEQ + r) * DH + dh, v[0], v[1]);
                    split_store_pair(hi_arr, lo_arr,
                                     ((size_t)hh * SEQ + r + 8) * DH + dh, v[2], v[3]);
                }
            }
        }
    }
}

// ---------------------------------------------------------------------------
// Flash attention, split-bf16 mma, cp.async double-buffered K/V tiles.
// CTA: 128 q rows (8 warps x 16), 64-wide KV tiles, causal.
// Dynamic smem: 2 stages x 32KB (Kh|Kl|Vh|Vl per stage); Q staged in stage 0
// before the pipeline starts.
// ---------------------------------------------------------------------------
__global__ __launch_bounds__(256)
void attn_mma(const bf16* __restrict__ Qh, const bf16* __restrict__ Ql,
              const bf16* __restrict__ Kh, const bf16* __restrict__ Kl,
              const bf16* __restrict__ Vh, const bf16* __restrict__ Vl,
              float* __restrict__ O)
{
    extern __shared__ __align__(128) uint8_t sm[];

    const int h   = blockIdx.y;
    const int qb  = (int)gridDim.x - 1 - (int)blockIdx.x;   // big blocks first
    const int q0  = qb * 128;
    const int tid = threadIdx.x;
    const int wid = tid >> 5;
    const int lane = tid & 31;

    const size_t hoff = (size_t)h * SEQ * DH;
    const uint32_t smbase = (uint32_t)__cvta_generic_to_shared(sm);

    // ---- stage Q hi/lo, pull A-fragments ----
    {
        const uint8_t* qsH = (const uint8_t*)(Qh + hoff + (size_t)q0 * DH);
        const uint8_t* qsL = (const uint8_t*)(Ql + hoff + (size_t)q0 * DH);
        for (int i = tid; i < 1024; i += 256) {
            int row = i >> 3, ch = i & 7;
            uint32_t off = row * 128 + ((ch ^ (row & 7)) << 4);
            *(uint4*)(sm + off)         = *(const uint4*)(qsH + row * 128 + ch * 16);
            *(uint4*)(sm + 16384 + off) = *(const uint4*)(qsL + row * 128 + ch * 16);
        }
    }
    __syncthreads();

    uint32_t qfh[4][4], qfl[4][4];
    {
        int row = wid * 16 + (lane & 7) + ((lane >> 3) & 1) * 8;
        int chs = lane >> 4;
        #pragma unroll
        for (int kt = 0; kt < 4; kt++) {
            int ch = 2 * kt + chs;
            uint32_t off = row * 128 + ((ch ^ (row & 7)) << 4);
            ldsm4(qfh[kt], smbase + off);
            ldsm4(qfl[kt], smbase + 16384 + off);
        }
    }
    __syncthreads();

    const uint8_t* kHp = (const uint8_t*)(Kh + hoff);
    const uint8_t* kLp = (const uint8_t*)(Kl + hoff);
    const uint8_t* vHp = (const uint8_t*)(Vh + hoff);
    const uint8_t* vLp = (const uint8_t*)(Vl + hoff);

    // cp.async tile fill: 64 rows x 128B, 4 arrays, per stage
    auto issue_tile = [&](int k0, int stage) {
        uint32_t sb = smbase + stage * 32768;
        #pragma unroll
        for (int i = tid; i < 512; i += 256) {
            int row = i >> 3, ch = i & 7;
            uint32_t off = row * 128 + ((ch ^ (row & 7)) << 4);
            size_t g = (size_t)(k0 + row) * 128 + ch * 16;
            cp16(sb + off,         kHp + g);
            cp16(sb +  8192 + off, kLp + g);
            cp16(sb + 16384 + off, vHp + g);
            cp16(sb + 24576 + off, vLp + g);
        }
    };

    float o[8][4];
    #pragma unroll
    for (int i = 0; i < 8; i++)
        #pragma unroll
        for (int j = 0; j < 4; j++) o[i][j] = 0.0f;
    float mr0 = -1e30f, mr1 = -1e30f, lr0 = 0.0f, lr1 = 0.0f;

    const int ntile = 2 * qb + 2;
    const int rmax  = q0 + wid * 16 + 15;
    const int r0g   = q0 + wid * 16 + (lane >> 2);

    issue_tile(0, 0);
    CP_COMMIT();

    for (int t = 0; t < ntile; t++) {
        const int k0 = t * 64;

        if (t + 1 < ntile) {
            issue_tile((t + 1) * 64, (t + 1) & 1);
            CP_COMMIT();
            CP_WAIT(1);
        } else {
            CP_WAIT(0);
        }
        __syncthreads();

        if (k0 <= rmax) {
            const uint32_t sb = smbase + (t & 1) * 32768;

            float s[8][4];
            #pragma unroll
            for (int nt = 0; nt < 8; nt++)
                #pragma unroll
                for (int j = 0; j < 4; j++) s[nt][j] = 0.0f;

            #pragma unroll
            for (int nt = 0; nt < 8; nt++) {
                uint32_t bh[8], bl[8];
                int row = nt * 8 + (lane & 7);
                {
                    int ch = lane >> 3;
                    uint32_t off = row * 128 + ((ch ^ (row & 7)) << 4);
                    ldsm4(bh,     sb + off);
                    ldsm4(bl,     sb + 8192 + off);
                    int ch2 = 4 + (lane >> 3);
                    uint32_t off2 = row * 128 + ((ch2 ^ (row & 7)) << 4);
                    ldsm4(bh + 4, sb + off2);
                    ldsm4(bl + 4, sb + 8192 + off2);
                }
                #pragma unroll
                for (int kt = 0; kt < 4; kt++) {
                    mma16816(s[nt], qfh[kt], bh + 2 * kt);
                    mma16816(s[nt], qfh[kt], bl + 2 * kt);
                    mma16816(s[nt], qfl[kt], bh + 2 * kt);
                }
            }

            if (k0 + 63 > q0 + wid * 16) {
                #pragma unroll
                for (int nt = 0; nt < 8; nt++) {
                    int c0 = k0 + nt * 8 + ((lane & 3) << 1);
                    if (c0     > r0g)     s[nt][0] = -1e30f;
                    if (c0 + 1 > r0g)     s[nt][1] = -1e30f;
                    if (c0     > r0g + 8) s[nt][2] = -1e30f;
                    if (c0 + 1 > r0g + 8) s[nt][3] = -1e30f;
                }
            }

            float mx0 = -1e30f, mx1 = -1e30f;
            #pragma unroll
            for (int nt = 0; nt < 8; nt++) {
                mx0 = fmaxf(mx0, fmaxf(s[nt][0], s[nt][1]));
                mx1 = fmaxf(mx1, fmaxf(s[nt][2], s[nt][3]));
            }
            mx0 = fmaxf(mx0, __shfl_xor_sync(0xffffffffu, mx0, 1));
            mx0 = fmaxf(mx0, __shfl_xor_sync(0xffffffffu, mx0, 2));
            mx1 = fmaxf(mx1, __shfl_xor_sync(0xffffffffu, mx1, 1));
            mx1 = fmaxf(mx1, __shfl_xor_sync(0xffffffffu, mx1, 2));

            float mn0 = fmaxf(mr0, mx0), mn1 = fmaxf(mr1, mx1);
            float c0 = __expf(mr0 - mn0), c1 = __expf(mr1 - mn1);
            mr0 = mn0; mr1 = mn1;

            float sum0 = 0.0f, sum1 = 0.0f;
            #pragma unroll
            for (int nt = 0; nt < 8; nt++) {
                s[nt][0] = __expf(s[nt][0] - mn0);
                s[nt][1] = __expf(s[nt][1] - mn0);
                s[nt][2] = __expf(s[nt][2] - mn1);
                s[nt][3] = __expf(s[nt][3] - mn1);
                sum0 += s[nt][0] + s[nt][1];
                sum1 += s[nt][2] + s[nt][3];
            }
            sum0 += __shfl_xor_sync(0xffffffffu, sum0, 1);
            sum0 += __shfl_xor_sync(0xffffffffu, sum0, 2);
            sum1 += __shfl_xor_sync(0xffffffffu, sum1, 1);
            sum1 += __shfl_xor_sync(0xffffffffu, sum1, 2);
            lr0 = lr0 * c0 + sum0;
            lr1 = lr1 * c1 + sum1;

            #pragma unroll
            for (int dt = 0; dt < 8; dt++) {
                o[dt][0] *= c0; o[dt][1] *= c0;
                o[dt][2] *= c1; o[dt][3] *= c1;
            }

            uint32_t pfh[4][4], pfl[4][4];
            #pragma unroll
            for (int kt = 0; kt < 4; kt++) {
                splitpack(s[2*kt][0],   s[2*kt][1],   pfh[kt][0], pfl[kt][0]);
                splitpack(s[2*kt][2],   s[2*kt][3],   pfh[kt][1], pfl[kt][1]);
                splitpack(s[2*kt+1][0], s[2*kt+1][1], pfh[kt][2], pfl[kt][2]);
                splitpack(s[2*kt+1][2], s[2*kt+1][3], pfh[kt][3], pfl[kt][3]);
            }

            #pragma unroll
            for (int dp = 0; dp < 4; dp++) {
                #pragma unroll
                for (int kt = 0; kt < 4; kt++) {
                    uint32_t vh4[4], vl4[4];
                    int vrow = kt * 16 + (lane & 7) + ((lane >> 3) & 1) * 8;
                    int ch = 2 * dp + (lane >> 4);
                    uint32_t off = vrow * 128 + ((ch ^ (vrow & 7)) << 4);
                    ldsm4t(vh4, sb + 16384 + off);
                    ldsm4t(vl4, sb + 24576 + off);
                    mma16816(o[2*dp],     pfh[kt], vh4);
                    mma16816(o[2*dp],     pfh[kt], vl4);
                    mma16816(o[2*dp],     pfl[kt], vh4);
                    mma16816(o[2*dp + 1], pfh[kt], vh4 + 2);
                    mma16816(o[2*dp + 1], pfh[kt], vl4 + 2);
                    mma16816(o[2*dp + 1], pfl[kt], vh4 + 2);
                }
            }
        }
        __syncthreads();
    }

    float i0 = 1.0f / lr0, i1 = 1.0f / lr1;
    int cb = h * DH + ((lane & 3) << 1);
    #pragma unroll
    for (int dt = 0; dt < 8; dt++) {
        *(float2*)&O[(size_t)r0g * DMODEL + cb + dt * 8] =
            make_float2(o[dt][0] * i0, o[dt][1] * i0);
        *(float2*)&O[(size_t)(r0g + 8) * DMODEL + cb + dt * 8] =
            make_float2(o[dt][2] * i1, o[dt][3] * i1);
    }
}

// ---------------------------------------------------------------------------
// kernel_launch — graph-capturable, allocation-free.
// ---------------------------------------------------------------------------
extern "C" void kernel_launch(void* const* d_in, const int* in_sizes, int n_in,
                              void* d_out, int out_size)
{
    const float* x   = (const float*)d_in[0];
    const float* wq  = (const float*)d_in[1];
    const float* wk  = (const float*)d_in[2];
    const float* wv  = (const float*)d_in[3];
    const float* wo  = (const float*)d_in[4];
    const int*   pos = (const int*)d_in[5];
    float* out = (float*)d_out;

    bf16 *qh, *ql, *kh, *kl, *vh, *vl;
    float *op, *cp, *sp;
    cudaGetSymbolAddress((void**)&qh, g_qh);
    cudaGetSymbolAddress((void**)&ql, g_ql);
    cudaGetSymbolAddress((void**)&kh, g_kh);
    cudaGetSymbolAddress((void**)&kl, g_kl);
    cudaGetSymbolAddress((void**)&vh, g_vh);
    cudaGetSymbolAddress((void**)&vl, g_vl);
    cudaGetSymbolAddress((void**)&op, g_o);
    cudaGetSymbolAddress((void**)&cp, g_cos);
    cudaGetSymbolAddress((void**)&sp, g_sin);

    const int smem_bytes = 65536;
    cudaFuncSetAttribute(gemm_mma<0>, cudaFuncAttributeMaxDynamicSharedMemorySize, smem_bytes);
    cudaFuncSetAttribute(gemm_mma<1>, cudaFuncAttributeMaxDynamicSharedMemorySize, smem_bytes);
    cudaFuncSetAttribute(attn_mma,    cudaFuncAttributeMaxDynamicSharedMemorySize, smem_bytes);

    // 1. RoPE cache
    rope_cache_kernel<<<(SEQ * HALF + 255) / 256, 256>>>(cp, sp);

    // 2. Fused QKV projections
    dim3 gq(DMODEL / 128, SEQ / 128, 3);
    gemm_mma<1><<<gq, 256, smem_bytes>>>(x, wq, wk, wv, nullptr,
                                         qh, ql, kh, kl, vh, vl, pos, cp, sp);

    // 3. Causal flash attention
    attn_mma<<<dim3(SEQ / 128, NH), 256, smem_bytes>>>(qh, ql, kh, kl, vh, vl, op);

    // 4. Output projection
    dim3 gg(DMODEL / 128, SEQ / 128, 1);
    gemm_mma<0><<<gg, 256, smem_bytes>>>(op, wo, nullptr, nullptr, out,
                                         nullptr, nullptr, nullptr, nullptr,
                                         nullptr, nullptr, nullptr, nullptr, nullptr);
}

// round 6
// speedup vs baseline: 3.4340x; 1.1697x over previous
#include <cuda_runtime.h>
#include <cuda_bf16.h>
#include <math.h>
#include <stdint.h>

using bf16 = __nv_bfloat16;

constexpr int SEQ    = 4096;
constexpr int DMODEL = 768;
constexpr int NH     = 12;
constexpr int DH     = 64;
constexpr int HALF   = DH / 2;   // 32
constexpr int WELEM  = DMODEL * DMODEL;

// Scratch (device globals; no runtime allocation allowed)
__device__ bf16  g_xh[SEQ * DMODEL];
__device__ bf16  g_xl[SEQ * DMODEL];
__device__ bf16  g_wh[4 * WELEM];
__device__ bf16  g_wl[4 * WELEM];
__device__ bf16  g_oh[SEQ * DMODEL];
__device__ bf16  g_ol[SEQ * DMODEL];
__device__ bf16  g_qh[NH * SEQ * DH];
__device__ bf16  g_ql[NH * SEQ * DH];
__device__ bf16  g_kh[NH * SEQ * DH];
__device__ bf16  g_kl[NH * SEQ * DH];
__device__ bf16  g_vh[NH * SEQ * DH];
__device__ bf16  g_vl[NH * SEQ * DH];
__device__ float g_cos[SEQ * HALF];
__device__ float g_sin[SEQ * HALF];

// ---------------------------------------------------------------------------
// RoPE cos/sin cache
// ---------------------------------------------------------------------------
__global__ void rope_cache_kernel(float* __restrict__ c, float* __restrict__ s)
{
    int i = blockIdx.x * blockDim.x + threadIdx.x;
    if (i >= SEQ * HALF) return;
    int p = i >> 5;
    int k = i & 31;
    float expo = -2.0f * (float)k / (float)DH;
    float invf = powf(10000.0f, expo);
    float ang  = (float)p * invf;
    c[i] = cosf(ang);
    s[i] = sinf(ang);
}

// ---------------------------------------------------------------------------
// bf16 split helpers
// ---------------------------------------------------------------------------
__device__ __forceinline__ void split_store_pair(bf16* __restrict__ hi_arr,
                                                 bf16* __restrict__ lo_arr,
                                                 size_t idx, float a, float b)
{
    __nv_bfloat162 h = __floats2bfloat162_rn(a, b);
    float ha = __bfloat162float(h.x);
    float hb = __bfloat162float(h.y);
    __nv_bfloat162 l = __floats2bfloat162_rn(a - ha, b - hb);
    *reinterpret_cast<__nv_bfloat162*>(hi_arr + idx) = h;
    *reinterpret_cast<__nv_bfloat162*>(lo_arr + idx) = l;
}

__device__ __forceinline__ void splitpack(float a, float b,
                                          uint32_t& hi, uint32_t& lo)
{
    __nv_bfloat162 h = __floats2bfloat162_rn(a, b);
    float ha = __bfloat162float(h.x);
    float hb = __bfloat162float(h.y);
    __nv_bfloat162 l = __floats2bfloat162_rn(a - ha, b - hb);
    hi = *reinterpret_cast<uint32_t*>(&h);
    lo = *reinterpret_cast<uint32_t*>(&l);
}

__device__ __forceinline__ void cvt8_split(const float4& p0, const float4& p1,
                                           uint4& hi, uint4& lo)
{
    uint32_t h0, l0, h1, l1, h2, l2, h3, l3;
    splitpack(p0.x, p0.y, h0, l0);
    splitpack(p0.z, p0.w, h1, l1);
    splitpack(p1.x, p1.y, h2, l2);
    splitpack(p1.z, p1.w, h3, l3);
    hi = make_uint4(h0, h1, h2, h3);
    lo = make_uint4(l0, l1, l2, l3);
}

// ---------------------------------------------------------------------------
// One-time fp32 -> bf16 hi/lo conversion of x and the 4 weights.
// grid: (1536, 5); y=0 -> x, y=1..4 -> wq,wk,wv,wo.
// ---------------------------------------------------------------------------
__global__ __launch_bounds__(256)
void convert_split_kernel(const float* __restrict__ x,
                          const float* __restrict__ wq, const float* __restrict__ wk,
                          const float* __restrict__ wv, const float* __restrict__ wo,
                          bf16* __restrict__ xh, bf16* __restrict__ xl,
                          bf16* __restrict__ wh, bf16* __restrict__ wl)
{
    int y = blockIdx.y;
    const float* src;
    bf16 *dh, *dl;
    int n;
    if (y == 0) { src = x;  dh = xh; dl = xl; n = SEQ * DMODEL; }
    else {
        src = (y == 1) ? wq : (y == 2) ? wk : (y == 3) ? wv : wo;
        dh = wh + (size_t)(y - 1) * WELEM;
        dl = wl + (size_t)(y - 1) * WELEM;
        n = WELEM;
    }
    int i = (blockIdx.x * 256 + threadIdx.x) * 8;
    if (i >= n) return;
    float4 a = *(const float4*)(src + i);
    float4 b = *(const float4*)(src + i + 4);
    uint4 hi, lo;
    cvt8_split(a, b, hi, lo);
    *(uint4*)(dh + i) = hi;
    *(uint4*)(dl + i) = lo;
}

// ---------------------------------------------------------------------------
// mma / ldmatrix / cp.async wrappers
// ---------------------------------------------------------------------------
__device__ __forceinline__ void ldsm4(uint32_t* r, uint32_t addr)
{
    asm volatile("ldmatrix.sync.aligned.m8n8.x4.shared.b16 {%0,%1,%2,%3}, [%4];"
        : "=r"(r[0]), "=r"(r[1]), "=r"(r[2]), "=r"(r[3]) : "r"(addr));
}
__device__ __forceinline__ void ldsm4t(uint32_t* r, uint32_t addr)
{
    asm volatile("ldmatrix.sync.aligned.m8n8.x4.trans.shared.b16 {%0,%1,%2,%3}, [%4];"
        : "=r"(r[0]), "=r"(r[1]), "=r"(r[2]), "=r"(r[3]) : "r"(addr));
}
__device__ __forceinline__ void mma16816(float* d, const uint32_t* a, const uint32_t* b)
{
    asm volatile(
        "mma.sync.aligned.m16n8k16.row.col.f32.bf16.bf16.f32 "
        "{%0,%1,%2,%3}, {%4,%5,%6,%7}, {%8,%9}, {%0,%1,%2,%3};"
        : "+f"(d[0]), "+f"(d[1]), "+f"(d[2]), "+f"(d[3])
        : "r"(a[0]), "r"(a[1]), "r"(a[2]), "r"(a[3]), "r"(b[0]), "r"(b[1]));
}
__device__ __forceinline__ void cp16(uint32_t dst, const void* src)
{
    asm volatile("cp.async.cg.shared.global [%0], [%1], 16;"
        :: "r"(dst), "l"(src));
}
#define CP_COMMIT() asm volatile("cp.async.commit_group;")
#define CP_WAIT(n)  asm volatile("cp.async.wait_group %0;" :: "n"(n))

// ---------------------------------------------------------------------------
// Split-bf16 NT GEMM on pre-split inputs: C = A(4096,768) @ B(768,768)^T.
// 3-term split: AhBh + AhBl + AlBh. Tile 128x128, K chunks of 32.
// 3-stage cp.async pipeline, 32KB/stage (Ah|Al|Bh|Bl 8KB each).
// 8 warps (4x2), warp tile 32x64, mma m16n8k16. 2 CTAs/SM target.
// MODE 0: fp32 store. MODE 1: QKV by blockIdx.z; RoPE for z<2; split scatter.
// ---------------------------------------------------------------------------
template<int MODE>
__global__ __launch_bounds__(256, 2)
void gemm_bf(const bf16* __restrict__ Agh, const bf16* __restrict__ Agl,
             const bf16* __restrict__ Wgh, const bf16* __restrict__ Wgl,
             float* __restrict__ Cout,
             bf16* __restrict__ qh, bf16* __restrict__ ql,
             bf16* __restrict__ kh, bf16* __restrict__ kl,
             bf16* __restrict__ vh, bf16* __restrict__ vl,
             const int* __restrict__ pos,
             const float* __restrict__ cosc, const float* __restrict__ sinc)
{
    constexpr int KD  = 768;
    constexpr int NCH = KD / 32;  // 24
    extern __shared__ __align__(128) uint8_t sm[];
    const uint32_t smb = (uint32_t)__cvta_generic_to_shared(sm);

    const int tid  = threadIdx.x;
    const int wid  = tid >> 5;
    const int lane = tid & 31;
    const int z    = (MODE == 1) ? blockIdx.z : 0;
    const bf16* Bgh = Wgh + (size_t)z * WELEM;
    const bf16* Bgl = Wgl + (size_t)z * WELEM;
    const int m0   = blockIdx.y * 128;
    const int n0   = blockIdx.x * 128;
    const int wm   = wid >> 1;
    const int wn   = wid & 1;

    float acc[2][8][4];
    #pragma unroll
    for (int m = 0; m < 2; m++)
        #pragma unroll
        for (int n = 0; n < 8; n++)
            #pragma unroll
            for (int j = 0; j < 4; j++) acc[m][n][j] = 0.0f;

    // stage layout: s*32768 + {Ah:0, Al:8192, Bh:16384, Bl:24576}
    // row = 64 bytes (32 bf16 = one k-chunk), 4x16B swizzled chunks
    auto cp_chunk = [&](int c, int s) {
        uint32_t base = smb + s * 32768;
        int kb = c * 32;
        #pragma unroll
        for (int it = 0; it < 2; it++) {
            int i   = it * 256 + tid;
            int row = i >> 2, o = i & 3;
            uint32_t off = (uint32_t)(row * 64 + ((o ^ (row & 3)) << 4));
            size_t ga = (size_t)(m0 + row) * KD + kb + o * 8;
            size_t gb = (size_t)(n0 + row) * KD + kb + o * 8;
            cp16(base + off,         Agh + ga);
            cp16(base +  8192 + off, Agl + ga);
            cp16(base + 16384 + off, Bgh + gb);
            cp16(base + 24576 + off, Bgl + gb);
        }
    };

    cp_chunk(0, 0); CP_COMMIT();
    cp_chunk(1, 1); CP_COMMIT();

    for (int c = 0; c < NCH; c++) {
        if (c < NCH - 1) { CP_WAIT(1); } else { CP_WAIT(0); }
        __syncthreads();
        if (c + 2 < NCH) { cp_chunk(c + 2, (c + 2) % 3); CP_COMMIT(); }

        const uint32_t sb = smb + (c % 3) * 32768;
        #pragma unroll
        for (int kt = 0; kt < 2; kt++) {
            uint32_t ah[2][4], al[2][4];
            #pragma unroll
            for (int m = 0; m < 2; m++) {
                int row = wm * 32 + m * 16 + (lane & 15);
                int ch  = kt * 2 + (lane >> 4);
                uint32_t off = (uint32_t)(row * 64 + ((ch ^ (row & 3)) << 4));
                ldsm4(ah[m], sb + off);
                ldsm4(al[m], sb + 8192 + off);
            }
            #pragma unroll
            for (int np = 0; np < 4; np++) {
                uint32_t bh4[4], bl4[4];
                int row = wn * 64 + np * 16 + (lane & 7) + ((lane >> 4) << 3);
                int ch  = kt * 2 + ((lane >> 3) & 1);
                uint32_t off = (uint32_t)(row * 64 + ((ch ^ (row & 3)) << 4));
                ldsm4(bh4, sb + 16384 + off);
                ldsm4(bl4, sb + 24576 + off);
                #pragma unroll
                for (int m = 0; m < 2; m++) {
                    mma16816(acc[m][2*np],     ah[m], bh4);
                    mma16816(acc[m][2*np],     ah[m], bl4);
                    mma16816(acc[m][2*np],     al[m], bh4);
                    mma16816(acc[m][2*np + 1], ah[m], bh4 + 2);
                    mma16816(acc[m][2*np + 1], ah[m], bl4 + 2);
                    mma16816(acc[m][2*np + 1], al[m], bh4 + 2);
                }
            }
        }
    }

    // ---- epilogue ----
    const int rbase = m0 + wm * 32 + (lane >> 2);
    const int cbase = n0 + wn * 64 + (lane & 3) * 2;

    if (MODE == 0) {
        #pragma unroll
        for (int m = 0; m < 2; m++)
            #pragma unroll
            for (int nt = 0; nt < 8; nt++) {
                const float* v = acc[m][nt];
                int r = rbase + m * 16;
                int c = cbase + nt * 8;
                *(float2*)&Cout[(size_t)r * DMODEL + c]       = make_float2(v[0], v[1]);
                *(float2*)&Cout[(size_t)(r + 8) * DMODEL + c] = make_float2(v[2], v[3]);
            }
    } else {
        bf16* hi_arr = (z == 0) ? qh : (z == 1) ? kh : vh;
        bf16* lo_arr = (z == 0) ? ql : (z == 1) ? kl : vl;
        const float scale = (z == 0) ? 0.125f : 1.0f;

        #pragma unroll
        for (int m = 0; m < 2; m++) {
            int r = rbase + m * 16;
            if (z < 2) {
                int p0 = pos[r], p1 = pos[r + 8];
                const float* cr0 = cosc + (size_t)p0 * HALF;
                const float* sr0 = sinc + (size_t)p0 * HALF;
                const float* cr1 = cosc + (size_t)p1 * HALF;
                const float* sr1 = sinc + (size_t)p1 * HALF;
                #pragma unroll
                for (int nt = 0; nt < 8; nt++) {
                    const float* v = acc[m][nt];
                    int c  = cbase + nt * 8;
                    int dh = c & 63;
                    int hh = c >> 6;
                    float cc = cr0[dh >> 1], ss = sr0[dh >> 1];
                    float re = (v[0] * cc - v[1] * ss) * scale;
                    float ro = (v[0] * ss + v[1] * cc) * scale;
                    split_store_pair(hi_arr, lo_arr,
                                     ((size_t)hh * SEQ + r) * DH + dh, re, ro);
                    cc = cr1[dh >> 1]; ss = sr1[dh >> 1];
                    re = (v[2] * cc - v[3] * ss) * scale;
                    ro = (v[2] * ss + v[3] * cc) * scale;
                    split_store_pair(hi_arr, lo_arr,
                                     ((size_t)hh * SEQ + r + 8) * DH + dh, re, ro);
                }
            } else {
                #pragma unroll
                for (int nt = 0; nt < 8; nt++) {
                    const float* v = acc[m][nt];
                    int c  = cbase + nt * 8;
                    int dh = c & 63;
                    int hh = c >> 6;
                    split_store_pair(hi_arr, lo_arr,
                                     ((size_t)hh * SEQ + r) * DH + dh, v[0], v[1]);
                    split_store_pair(hi_arr, lo_arr,
                                     ((size_t)hh * SEQ + r + 8) * DH + dh, v[2], v[3]);
                }
            }
        }
    }
}

// ---------------------------------------------------------------------------
// Flash attention, split-bf16 mma, cp.async double-buffered K/V tiles.
// Epilogue split-stores O to bf16 hi/lo for the out-projection.
// ---------------------------------------------------------------------------
__global__ __launch_bounds__(256)
void attn_mma(const bf16* __restrict__ Qh, const bf16* __restrict__ Ql,
              const bf16* __restrict__ Kh, const bf16* __restrict__ Kl,
              const bf16* __restrict__ Vh, const bf16* __restrict__ Vl,
              bf16* __restrict__ Oh, bf16* __restrict__ Ol)
{
    extern __shared__ __align__(128) uint8_t sm[];

    const int h   = blockIdx.y;
    const int qb  = (int)gridDim.x - 1 - (int)blockIdx.x;   // big blocks first
    const int q0  = qb * 128;
    const int tid = threadIdx.x;
    const int wid = tid >> 5;
    const int lane = tid & 31;

    const size_t hoff = (size_t)h * SEQ * DH;
    const uint32_t smbase = (uint32_t)__cvta_generic_to_shared(sm);

    {
        const uint8_t* qsH = (const uint8_t*)(Qh + hoff + (size_t)q0 * DH);
        const uint8_t* qsL = (const uint8_t*)(Ql + hoff + (size_t)q0 * DH);
        for (int i = tid; i < 1024; i += 256) {
            int row = i >> 3, ch = i & 7;
            uint32_t off = row * 128 + ((ch ^ (row & 7)) << 4);
            *(uint4*)(sm + off)         = *(const uint4*)(qsH + row * 128 + ch * 16);
            *(uint4*)(sm + 16384 + off) = *(const uint4*)(qsL + row * 128 + ch * 16);
        }
    }
    __syncthreads();

    uint32_t qfh[4][4], qfl[4][4];
    {
        int row = wid * 16 + (lane & 15);
        int chs = lane >> 4;
        #pragma unroll
        for (int kt = 0; kt < 4; kt++) {
            int ch = 2 * kt + chs;
            uint32_t off = row * 128 + ((ch ^ (row & 7)) << 4);
            ldsm4(qfh[kt], smbase + off);
            ldsm4(qfl[kt], smbase + 16384 + off);
        }
    }
    __syncthreads();

    const uint8_t* kHp = (const uint8_t*)(Kh + hoff);
    const uint8_t* kLp = (const uint8_t*)(Kl + hoff);
    const uint8_t* vHp = (const uint8_t*)(Vh + hoff);
    const uint8_t* vLp = (const uint8_t*)(Vl + hoff);

    auto issue_tile = [&](int k0, int stage) {
        uint32_t sb = smbase + stage * 32768;
        #pragma unroll
        for (int i = tid; i < 512; i += 256) {
            int row = i >> 3, ch = i & 7;
            uint32_t off = row * 128 + ((ch ^ (row & 7)) << 4);
            size_t g = (size_t)(k0 + row) * 128 + ch * 16;
            cp16(sb + off,         kHp + g);
            cp16(sb +  8192 + off, kLp + g);
            cp16(sb + 16384 + off, vHp + g);
            cp16(sb + 24576 + off, vLp + g);
        }
    };

    float o[8][4];
    #pragma unroll
    for (int i = 0; i < 8; i++)
        #pragma unroll
        for (int j = 0; j < 4; j++) o[i][j] = 0.0f;
    float mr0 = -1e30f, mr1 = -1e30f, lr0 = 0.0f, lr1 = 0.0f;

    const int ntile = 2 * qb + 2;
    const int rmax  = q0 + wid * 16 + 15;
    const int r0g   = q0 + wid * 16 + (lane >> 2);

    issue_tile(0, 0);
    CP_COMMIT();

    for (int t = 0; t < ntile; t++) {
        const int k0 = t * 64;

        if (t + 1 < ntile) {
            issue_tile((t + 1) * 64, (t + 1) & 1);
            CP_COMMIT();
            CP_WAIT(1);
        } else {
            CP_WAIT(0);
        }
        __syncthreads();

        if (k0 <= rmax) {
            const uint32_t sb = smbase + (t & 1) * 32768;

            float s[8][4];
            #pragma unroll
            for (int nt = 0; nt < 8; nt++)
                #pragma unroll
                for (int j = 0; j < 4; j++) s[nt][j] = 0.0f;

            #pragma unroll
            for (int nt = 0; nt < 8; nt++) {
                uint32_t bh[8], bl[8];
                int row = nt * 8 + (lane & 7);
                {
                    int ch = lane >> 3;
                    uint32_t off = row * 128 + ((ch ^ (row & 7)) << 4);
                    ldsm4(bh,     sb + off);
                    ldsm4(bl,     sb + 8192 + off);
                    int ch2 = 4 + (lane >> 3);
                    uint32_t off2 = row * 128 + ((ch2 ^ (row & 7)) << 4);
                    ldsm4(bh + 4, sb + off2);
                    ldsm4(bl + 4, sb + 8192 + off2);
                }
                #pragma unroll
                for (int kt = 0; kt < 4; kt++) {
                    mma16816(s[nt], qfh[kt], bh + 2 * kt);
                    mma16816(s[nt], qfh[kt], bl + 2 * kt);
                    mma16816(s[nt], qfl[kt], bh + 2 * kt);
                }
            }

            if (k0 + 63 > q0 + wid * 16) {
                #pragma unroll
                for (int nt = 0; nt < 8; nt++) {
                    int c0 = k0 + nt * 8 + ((lane & 3) << 1);
                    if (c0     > r0g)     s[nt][0] = -1e30f;
                    if (c0 + 1 > r0g)     s[nt][1] = -1e30f;
                    if (c0     > r0g + 8) s[nt][2] = -1e30f;
                    if (c0 + 1 > r0g + 8) s[nt][3] = -1e30f;
                }
            }

            float mx0 = -1e30f, mx1 = -1e30f;
            #pragma unroll
            for (int nt = 0; nt < 8; nt++) {
                mx0 = fmaxf(mx0, fmaxf(s[nt][0], s[nt][1]));
                mx1 = fmaxf(mx1, fmaxf(s[nt][2], s[nt][3]));
            }
            mx0 = fmaxf(mx0, __shfl_xor_sync(0xffffffffu, mx0, 1));
            mx0 = fmaxf(mx0, __shfl_xor_sync(0xffffffffu, mx0, 2));
            mx1 = fmaxf(mx1, __shfl_xor_sync(0xffffffffu, mx1, 1));
            mx1 = fmaxf(mx1, __shfl_xor_sync(0xffffffffu, mx1, 2));

            float mn0 = fmaxf(mr0, mx0), mn1 = fmaxf(mr1, mx1);
            float c0 = __expf(mr0 - mn0), c1 = __expf(mr1 - mn1);
            mr0 = mn0; mr1 = mn1;

            float sum0 = 0.0f, sum1 = 0.0f;
            #pragma unroll
            for (int nt = 0; nt < 8; nt++) {
                s[nt][0] = __expf(s[nt][0] - mn0);
                s[nt][1] = __expf(s[nt][1] - mn0);
                s[nt][2] = __expf(s[nt][2] - mn1);
                s[nt][3] = __expf(s[nt][3] - mn1);
                sum0 += s[nt][0] + s[nt][1];
                sum1 += s[nt][2] + s[nt][3];
            }
            sum0 += __shfl_xor_sync(0xffffffffu, sum0, 1);
            sum0 += __shfl_xor_sync(0xffffffffu, sum0, 2);
            sum1 += __shfl_xor_sync(0xffffffffu, sum1, 1);
            sum1 += __shfl_xor_sync(0xffffffffu, sum1, 2);
            lr0 = lr0 * c0 + sum0;
            lr1 = lr1 * c1 + sum1;

            #pragma unroll
            for (int dt = 0; dt < 8; dt++) {
                o[dt][0] *= c0; o[dt][1] *= c0;
                o[dt][2] *= c1; o[dt][3] *= c1;
            }

            uint32_t pfh[4][4], pfl[4][4];
            #pragma unroll
            for (int kt = 0; kt < 4; kt++) {
                splitpack(s[2*kt][0],   s[2*kt][1],   pfh[kt][0], pfl[kt][0]);
                splitpack(s[2*kt][2],   s[2*kt][3],   pfh[kt][1], pfl[kt][1]);
                splitpack(s[2*kt+1][0], s[2*kt+1][1], pfh[kt][2], pfl[kt][2]);
                splitpack(s[2*kt+1][2], s[2*kt+1][3], pfh[kt][3], pfl[kt][3]);
            }

            #pragma unroll
            for (int dp = 0; dp < 4; dp++) {
                #pragma unroll
                for (int kt = 0; kt < 4; kt++) {
                    uint32_t vh4[4], vl4[4];
                    int vrow = kt * 16 + (lane & 15);
                    int ch = 2 * dp + (lane >> 4);
                    uint32_t off = vrow * 128 + ((ch ^ (vrow & 7)) << 4);
                    ldsm4t(vh4, sb + 16384 + off);
                    ldsm4t(vl4, sb + 24576 + off);
                    mma16816(o[2*dp],     pfh[kt], vh4);
                    mma16816(o[2*dp],     pfh[kt], vl4);
                    mma16816(o[2*dp],     pfl[kt], vh4);
                    mma16816(o[2*dp + 1], pfh[kt], vh4 + 2);
                    mma16816(o[2*dp + 1], pfh[kt], vl4 + 2);
                    mma16816(o[2*dp + 1], pfl[kt], vh4 + 2);
                }
            }
        }
        __syncthreads();
    }

    float i0 = 1.0f / lr0, i1 = 1.0f / lr1;
    int cb = h * DH + ((lane & 3) << 1);
    #pragma unroll
    for (int dt = 0; dt < 8; dt++) {
        split_store_pair(Oh, Ol, (size_t)r0g * DMODEL + cb + dt * 8,
                         o[dt][0] * i0, o[dt][1] * i0);
        split_store_pair(Oh, Ol, (size_t)(r0g + 8) * DMODEL + cb + dt * 8,
                         o[dt][2] * i1, o[dt][3] * i1);
    }
}

// ---------------------------------------------------------------------------
// kernel_launch — graph-capturable, allocation-free.
// ---------------------------------------------------------------------------
extern "C" void kernel_launch(void* const* d_in, const int* in_sizes, int n_in,
                              void* d_out, int out_size)
{
    const float* x   = (const float*)d_in[0];
    const float* wq  = (const float*)d_in[1];
    const float* wk  = (const float*)d_in[2];
    const float* wv  = (const float*)d_in[3];
    const float* wo  = (const float*)d_in[4];
    const int*   pos = (const int*)d_in[5];
    float* out = (float*)d_out;

    bf16 *xh, *xl, *wh, *wl, *oh, *ol;
    bf16 *qh, *ql, *kh, *kl, *vh, *vl;
    float *cp, *sp;
    cudaGetSymbolAddress((void**)&xh, g_xh);
    cudaGetSymbolAddress((void**)&xl, g_xl);
    cudaGetSymbolAddress((void**)&wh, g_wh);
    cudaGetSymbolAddress((void**)&wl, g_wl);
    cudaGetSymbolAddress((void**)&oh, g_oh);
    cudaGetSymbolAddress((void**)&ol, g_ol);
    cudaGetSymbolAddress((void**)&qh, g_qh);
    cudaGetSymbolAddress((void**)&ql, g_ql);
    cudaGetSymbolAddress((void**)&kh, g_kh);
    cudaGetSymbolAddress((void**)&kl, g_kl);
    cudaGetSymbolAddress((void**)&vh, g_vh);
    cudaGetSymbolAddress((void**)&vl, g_vl);
    cudaGetSymbolAddress((void**)&cp, g_cos);
    cudaGetSymbolAddress((void**)&sp, g_sin);

    const int gemm_smem = 3 * 32768;   // 98304
    const int attn_smem = 65536;
    cudaFuncSetAttribute(gemm_bf<0>, cudaFuncAttributeMaxDynamicSharedMemorySize, gemm_smem);
    cudaFuncSetAttribute(gemm_bf<1>, cudaFuncAttributeMaxDynamicSharedMemorySize, gemm_smem);
    cudaFuncSetAttribute(attn_mma,   cudaFuncAttributeMaxDynamicSharedMemorySize, attn_smem);

    // 1. RoPE cache + one-time hi/lo split of x and weights
    rope_cache_kernel<<<(SEQ * HALF + 255) / 256, 256>>>(cp, sp);
    convert_split_kernel<<<dim3((SEQ * DMODEL / 8 + 255) / 256, 5), 256>>>(
        x, wq, wk, wv, wo, xh, xl, wh, wl);

    // 2. QKV projections (pre-split bf16 mma, RoPE + split epilogue)
    dim3 gq(DMODEL / 128, SEQ / 128, 3);
    gemm_bf<1><<<gq, 256, gemm_smem>>>(xh, xl, wh, wl, nullptr,
                                       qh, ql, kh, kl, vh, vl, pos, cp, sp);

    // 3. Causal flash attention
    attn_mma<<<dim3(SEQ / 128, NH), 256, attn_smem>>>(qh, ql, kh, kl, vh, vl, oh, ol);

    // 4. Output projection (wo = weight index 3), fp32 store
    dim3 gg(DMODEL / 128, SEQ / 128, 1);
    gemm_bf<0><<<gg, 256, gemm_smem>>>(oh, ol, wh + (size_t)3 * WELEM, wl + (size_t)3 * WELEM,
                                       out, nullptr, nullptr, nullptr, nullptr,
                                       nullptr, nullptr, nullptr, nullptr, nullptr);
}